// round 11
// baseline (speedup 1.0000x reference)
#include <cuda_runtime.h>
#include <cuda_bf16.h>
#include <math.h>
#include <stdint.h>

#define NS    3200
#define NQ    200000
#define NTOT  203200        // NS + NQ
#define INF_  512
#define DD    128
#define CC    64
#define NTILES   (NTOT/64)  // 3175
#define QTILES   (NQ/64)    // 3125
#define MTILES   ((NTOT + 127) / 128)   // 1588

// ---------------- scratch (device globals; no allocation allowed) ----------
__device__ float g_embS[(size_t)NS * DD];        // fp32 support embeddings
__device__ __nv_bfloat16 g_embh[(size_t)NTOT * DD];  // emb hi
__device__ __nv_bfloat16 g_embl[(size_t)NTOT * DD];  // emb lo
__device__ float g_e2[NTOT];                 // per-row squared norms
__device__ float g_proto[CC * DD];           // prototypes fp32 [64][128]
__device__ __nv_bfloat16 g_ph[CC * DD];      // proto hi
__device__ __nv_bfloat16 g_pl[CC * DD];      // proto lo
__device__ float g_p2[CC];                   // proto squared norms
__device__ float g_sums[CC * DD];            // accumulation buffer
__device__ __nv_bfloat16 g_whi[INF_ * DD];   // W hi  [512][128]
__device__ __nv_bfloat16 g_wlo[INF_ * DD];   // W lo  [512][128]

// ================= helpers ==================================================
__device__ __forceinline__ uint32_t smem_u32(const void* p) {
    uint32_t a;
    asm("{ .reg .u64 t; cvta.to.shared.u64 t, %1; cvt.u32.u64 %0, t; }"
        : "=r"(a) : "l"(p));
    return a;
}
__device__ __forceinline__ void mma16816(float* d, const uint32_t* a, const uint32_t* b) {
    asm volatile(
        "mma.sync.aligned.m16n8k16.row.col.f32.bf16.bf16.f32 "
        "{%0,%1,%2,%3}, {%4,%5,%6,%7}, {%8,%9}, {%0,%1,%2,%3};\n"
        : "+f"(d[0]), "+f"(d[1]), "+f"(d[2]), "+f"(d[3])
        : "r"(a[0]), "r"(a[1]), "r"(a[2]), "r"(a[3]), "r"(b[0]), "r"(b[1]));
}
__device__ __forceinline__ void ldm_x4(uint32_t* r, uint32_t addr) {
    asm volatile("ldmatrix.sync.aligned.m8n8.x4.shared.b16 {%0,%1,%2,%3}, [%4];\n"
                 : "=r"(r[0]), "=r"(r[1]), "=r"(r[2]), "=r"(r[3]) : "r"(addr));
}
__device__ __forceinline__ void ldm_x4_t(uint32_t* r, uint32_t addr) {
    asm volatile("ldmatrix.sync.aligned.m8n8.x4.trans.shared.b16 {%0,%1,%2,%3}, [%4];\n"
                 : "=r"(r[0]), "=r"(r[1]), "=r"(r[2]), "=r"(r[3]) : "r"(addr));
}
__device__ __forceinline__ uint32_t pack2(__nv_bfloat16 a, __nv_bfloat16 b) {
    return ((uint32_t)__bfloat16_as_ushort(b) << 16) | (uint32_t)__bfloat16_as_ushort(a);
}
__device__ __forceinline__ void split1(float x, __nv_bfloat16& h, __nv_bfloat16& l) {
    h = __float2bfloat16_rn(x);
    l = __float2bfloat16_rn(x - __bfloat162float(h));
}

// ---------------- 0. W convert (hi/lo split, natural [K][N] layout) ---------
__global__ void k_wconv(const float* __restrict__ W) {
    int i = blockIdx.x * blockDim.x + threadIdx.x;
    if (i < INF_ * DD) {
        __nv_bfloat16 h, l;
        split1(W[i], h, l);
        g_whi[i] = h;
        g_wlo[i] = l;
    }
}

// ---------------- 1. embedding GEMM via mma.sync bf16 (fp32-split) ----------
// R6 dataflow (LDG->split->STS, single buffer) but 512 threads / 16 warps:
// warp grid 4x4, warp tile 32 rows x 32 cols -> 4 warps/SMSP for latency hiding.
// smem (halves): Ahi[128][72], Alo[128][72], Bhi[64][136], Blo[64][136]
#define A_STR 72
#define B_STR 136
#define AHI_OFF 0
#define ALO_OFF (128 * A_STR)
#define BHI_OFF (2 * 128 * A_STR)
#define BLO_OFF (BHI_OFF + 64 * B_STR)
#define EMB_SMEM_HALVES (BLO_OFF + 64 * B_STR)
#define EMB_SMEM_BYTES  (EMB_SMEM_HALVES * 2)   // 71680
#define C_STR 132

__global__ __launch_bounds__(512)
void k_embed_mma(const float* __restrict__ sup, const float* __restrict__ qry,
                 const float* __restrict__ bias) {
    extern __shared__ char smraw[];
    __nv_bfloat16* sh = (__nv_bfloat16*)smraw;
    float* shf = (float*)smraw;
    const uint32_t sbase = smem_u32(smraw);

    const int t = threadIdx.x;
    const int wid = t >> 5, lane = t & 31;
    const int warp_m = wid & 3;               // rows warp_m*32
    const int warp_n = wid >> 2;              // cols warp_n*32 (0..3)
    const int m0 = blockIdx.x * 128;
    const int lr = lane & 15;
    const int lc = lane >> 4;

    float acc[2][4][4];
#pragma unroll
    for (int i = 0; i < 2; i++)
#pragma unroll
        for (int j = 0; j < 4; j++)
#pragma unroll
            for (int q = 0; q < 4; q++) acc[i][j][q] = 0.f;

    for (int kb = 0; kb < 8; kb++) {
        const int k0 = kb * 64;
        __syncthreads();
        // ---- A: 128 rows x 64 k fp32 -> split -> STS (2048 float4, 4/thread) ----
#pragma unroll
        for (int p = 0; p < 4; p++) {
            int l = t + 512 * p;
            int r = l >> 4, q = l & 15;
            int row = m0 + r;
            if (row >= NTOT) row = NTOT - 1;
            const float* src = (row < NS) ? (sup + (size_t)row * INF_)
                                          : (qry + (size_t)(row - NS) * INF_);
            float4 v = *(const float4*)(src + k0 + q * 4);
            __nv_bfloat16 h0, l0, h1, l1, h2, l2, h3, l3;
            split1(v.x, h0, l0); split1(v.y, h1, l1);
            split1(v.z, h2, l2); split1(v.w, h3, l3);
            *(uint2*)&sh[AHI_OFF + r * A_STR + q * 4] =
                make_uint2(pack2(h0, h1), pack2(h2, h3));
            *(uint2*)&sh[ALO_OFF + r * A_STR + q * 4] =
                make_uint2(pack2(l0, l1), pack2(l2, l3));
        }
        // ---- B: 64 k-rows x 128 n halves, hi+lo (1024 uint4 each, 2/thread) ----
#pragma unroll
        for (int p = 0; p < 2; p++) {
            int l = t + 512 * p;
            int kr = l >> 4, ch = l & 15;
            *(uint4*)&sh[BHI_OFF + kr * B_STR + ch * 8] =
                *(const uint4*)(g_whi + (size_t)(k0 + kr) * DD + ch * 8);
            *(uint4*)&sh[BLO_OFF + kr * B_STR + ch * 8] =
                *(const uint4*)(g_wlo + (size_t)(k0 + kr) * DD + ch * 8);
        }
        __syncthreads();

        // ---- compute 4 k16 steps; warp tile 32x32 ----
#pragma unroll
        for (int ks = 0; ks < 4; ks++) {
            const int kk = ks * 16;
            uint32_t bh[4][2], bl[4][2];
#pragma unroll
            for (int nb = 0; nb < 2; nb++) {
                uint32_t r4[4];
                uint32_t addr = sbase + 2 * (BHI_OFF + (kk + lr) * B_STR
                                 + warp_n * 32 + nb * 16 + lc * 8);
                ldm_x4_t(r4, addr);
                bh[nb * 2][0] = r4[0]; bh[nb * 2][1] = r4[1];
                bh[nb * 2 + 1][0] = r4[2]; bh[nb * 2 + 1][1] = r4[3];
                addr = sbase + 2 * (BLO_OFF + (kk + lr) * B_STR
                                 + warp_n * 32 + nb * 16 + lc * 8);
                ldm_x4_t(r4, addr);
                bl[nb * 2][0] = r4[0]; bl[nb * 2][1] = r4[1];
                bl[nb * 2 + 1][0] = r4[2]; bl[nb * 2 + 1][1] = r4[3];
            }
#pragma unroll
            for (int fm = 0; fm < 2; fm++) {
                uint32_t ah[4], al[4];
                int arow = warp_m * 32 + fm * 16 + lr;
                ldm_x4(ah, sbase + 2 * (AHI_OFF + arow * A_STR + kk + lc * 8));
                ldm_x4(al, sbase + 2 * (ALO_OFF + arow * A_STR + kk + lc * 8));
#pragma unroll
                for (int fn = 0; fn < 4; fn++) {
                    mma16816(acc[fm][fn], ah, bh[fn]);
                    mma16816(acc[fm][fn], ah, bl[fn]);
                    mma16816(acc[fm][fn], al, bh[fn]);
                }
            }
        }
    }

    // ---- epilogue: stage C via smem; bias; fp32 (support) + bf16 hi/lo + e2 ----
    __syncthreads();
#pragma unroll
    for (int fm = 0; fm < 2; fm++)
#pragma unroll
        for (int fn = 0; fn < 4; fn++) {
            int r0 = warp_m * 32 + fm * 16 + (lane >> 2);
            int c0 = warp_n * 32 + fn * 8 + (lane & 3) * 2;
            shf[r0 * C_STR + c0]           = acc[fm][fn][0];
            shf[r0 * C_STR + c0 + 1]       = acc[fm][fn][1];
            shf[(r0 + 8) * C_STR + c0]     = acc[fm][fn][2];
            shf[(r0 + 8) * C_STR + c0 + 1] = acc[fm][fn][3];
        }
    __syncthreads();
    {
        const int r = t >> 2, qd = t & 3;     // thread covers cols qd*32..qd*32+31
        const int row = m0 + r;
        const int cb = qd * 32;
        float e2 = 0.f;
        if (row < NTOT) {
            const float* srow = &shf[r * C_STR + cb];
            __nv_bfloat16* dh = g_embh + (size_t)row * DD + cb;
            __nv_bfloat16* dl = g_embl + (size_t)row * DD + cb;
#pragma unroll
            for (int j = 0; j < 32; j += 4) {
                float4 o;
                o.x = srow[j + 0] + __ldg(bias + cb + j + 0);
                o.y = srow[j + 1] + __ldg(bias + cb + j + 1);
                o.z = srow[j + 2] + __ldg(bias + cb + j + 2);
                o.w = srow[j + 3] + __ldg(bias + cb + j + 3);
                if (row < NS)
                    *(float4*)(g_embS + (size_t)row * DD + cb + j) = o;
                __nv_bfloat16 h0, l0, h1, l1, h2, l2, h3, l3;
                split1(o.x, h0, l0); split1(o.y, h1, l1);
                split1(o.z, h2, l2); split1(o.w, h3, l3);
                *(uint2*)(dh + j) = make_uint2(pack2(h0, h1), pack2(h2, h3));
                *(uint2*)(dl + j) = make_uint2(pack2(l0, l1), pack2(l2, l3));
                e2 += o.x * o.x + o.y * o.y + o.z * o.z + o.w * o.w;
            }
        }
        e2 += __shfl_xor_sync(0xffffffffu, e2, 1);
        e2 += __shfl_xor_sync(0xffffffffu, e2, 2);
        if (qd == 0 && row < NTOT) g_e2[row] = e2;
    }
}

// ---------------- 2. initial prototypes: segment mean (+ zero g_sums) ------
__global__ __launch_bounds__(128) void k_init(const int* __restrict__ lab) {
    __shared__ float red[128];
    const int c = blockIdx.x, d = threadIdx.x;
    g_sums[c * DD + d] = 0.f;
    float sum = 0.f; int cnt = 0;
    for (int n = 0; n < NS; n++) {
        if (__ldg(&lab[n]) == c) { sum += g_embS[(size_t)n * DD + d]; cnt++; }
    }
    float p = sum / fmaxf((float)cnt, 1.0f);
    g_proto[c * DD + d] = p;
    __nv_bfloat16 h, l;
    split1(p, h, l);
    g_ph[c * DD + d] = h;
    g_pl[c * DD + d] = l;
    red[d] = p * p;
    __syncthreads();
    for (int o = 64; o > 0; o >>= 1) {
        if (d < o) red[d] += red[d + o];
        __syncthreads();
    }
    if (d == 0) g_p2[c] = red[0];
}

// ---------------- 3b. fused attention + prototype accumulation (mma) -------
// HI-ONLY in-loop precision (rel_err validated identical in R8/R9/R10).
#define FP32_BYTES 17152
#define PPH_OFF 0
#define PEH_OFF 8704
#define PAH_OFF 17408
#define PROP_SMEM (FP32_BYTES + (17408 + 64 * 72) * 2)   // 61184
#define P_STR 136
#define AT_STR 72
#define PH_OFF 0
#define PL_OFF 8704
#define EH_OFF 17408
#define EL_OFF 26112
#define LOG_SMEM (FP32_BYTES + 34816 * 2)                // 86784
#define PROP_GRID 444

__global__ __launch_bounds__(256) void k_prop() {
    extern __shared__ char sm[];
    float* S_sh = (float*)sm;                // [64][65]
    float* e2_s = S_sh + 64 * 65;
    float* p2_s = e2_s + 64;
    __nv_bfloat16* hb = (__nv_bfloat16*)(sm + FP32_BYTES);
    const uint32_t hbase = smem_u32(sm) + FP32_BYTES;

    const int t = threadIdx.x, wid = t >> 5, lane = t & 31;
    const int lr = lane & 15, lc = lane >> 4;
    const int warp_m = wid & 3, warp_n = wid >> 2;

    for (int l = t; l < 64 * 16; l += 256) {
        int r = l >> 4, ch = l & 15;
        *(uint4*)&hb[PPH_OFF + r * P_STR + ch * 8] = *(const uint4*)(g_ph + r * DD + ch * 8);
    }
    if (t < 64) p2_s[t] = g_p2[t];

    float acc[8][4];
#pragma unroll
    for (int j = 0; j < 8; j++)
#pragma unroll
        for (int q = 0; q < 4; q++) acc[j][q] = 0.f;

    for (int tile = blockIdx.x; tile < NTILES; tile += gridDim.x) {
        const int row0 = tile * 64;
        __syncthreads();
        for (int l = t; l < 64 * 16; l += 256) {
            int r = l >> 4, ch = l & 15;
            *(uint4*)&hb[PEH_OFF + r * P_STR + ch * 8] =
                *(const uint4*)(g_embh + (size_t)(row0 + r) * DD + ch * 8);
        }
        if (t < 64) e2_s[t] = g_e2[row0 + t];
        __syncthreads();

        float sacc[4][4];
#pragma unroll
        for (int i = 0; i < 4; i++)
#pragma unroll
            for (int j = 0; j < 4; j++) sacc[i][j] = 0.f;
#pragma unroll
        for (int ks = 0; ks < 8; ks++) {
            const int kk = ks * 16;
            uint32_t ah4[4];
            ldm_x4(ah4, hbase + 2 * (PEH_OFF + (warp_m * 16 + lr) * P_STR + kk + lc * 8));
            uint32_t bh[4][2];
#pragma unroll
            for (int nb = 0; nb < 2; nb++) {
                uint32_t r4[4];
                ldm_x4(r4, hbase + 2 * (PPH_OFF + (warp_n * 32 + nb * 16 + lr) * P_STR + kk + lc * 8));
                bh[nb * 2][0] = r4[0]; bh[nb * 2][1] = r4[2];
                bh[nb * 2 + 1][0] = r4[1]; bh[nb * 2 + 1][1] = r4[3];
            }
#pragma unroll
            for (int fn = 0; fn < 4; fn++)
                mma16816(sacc[fn], ah4, bh[fn]);
        }
        {
            const int rr = warp_m * 16 + (lane >> 2);
#pragma unroll
            for (int fn = 0; fn < 4; fn++) {
                const int cc = warp_n * 32 + fn * 8 + (lane & 3) * 2;
                S_sh[rr * 65 + cc] =
                    sqrtf(fmaxf(e2_s[rr] + p2_s[cc] - 2.f * sacc[fn][0], 0.f));
                S_sh[rr * 65 + cc + 1] =
                    sqrtf(fmaxf(e2_s[rr] + p2_s[cc + 1] - 2.f * sacc[fn][1], 0.f));
                S_sh[(rr + 8) * 65 + cc] =
                    sqrtf(fmaxf(e2_s[rr + 8] + p2_s[cc] - 2.f * sacc[fn][2], 0.f));
                S_sh[(rr + 8) * 65 + cc + 1] =
                    sqrtf(fmaxf(e2_s[rr + 8] + p2_s[cc + 1] - 2.f * sacc[fn][3], 0.f));
            }
        }
        __syncthreads();

        {
            const int r = t >> 2, sg = t & 3;
            const int cbase = sg * 16;
            float mn = 1e30f;
#pragma unroll
            for (int i = 0; i < 16; i++) mn = fminf(mn, S_sh[r * 65 + cbase + i]);
            mn = fminf(mn, __shfl_xor_sync(0xffffffffu, mn, 1));
            mn = fminf(mn, __shfl_xor_sync(0xffffffffu, mn, 2));
            float w[16];
            float s = 0.f;
#pragma unroll
            for (int i = 0; i < 16; i++) {
                w[i] = __expf(mn - S_sh[r * 65 + cbase + i]);
                s += w[i];
            }
            s += __shfl_xor_sync(0xffffffffu, s, 1);
            s += __shfl_xor_sync(0xffffffffu, s, 2);
            const float inv = 1.0f / s;
#pragma unroll
            for (int i = 0; i < 16; i += 2)
                *(uint32_t*)&hb[PAH_OFF + r * AT_STR + cbase + i] =
                    pack2(__float2bfloat16_rn(w[i] * inv),
                          __float2bfloat16_rn(w[i + 1] * inv));
        }
        __syncthreads();

#pragma unroll
        for (int ks = 0; ks < 4; ks++) {
            const int kk = ks * 16;
            uint32_t r4[4];
            uint32_t aa_h[4];
            ldm_x4_t(r4, hbase + 2 * (PAH_OFF + (kk + lr) * AT_STR + warp_m * 16 + lc * 8));
            aa_h[0] = r4[0]; aa_h[1] = r4[2]; aa_h[2] = r4[1]; aa_h[3] = r4[3];
#pragma unroll
            for (int nb = 0; nb < 4; nb++) {
                uint32_t e4[4];
                uint32_t beh0[2], beh1[2];
                ldm_x4_t(e4, hbase + 2 * (PEH_OFF + (kk + lr) * P_STR + warp_n * 64 + nb * 16 + lc * 8));
                beh0[0] = e4[0]; beh0[1] = e4[1];
                beh1[0] = e4[2]; beh1[1] = e4[3];
                mma16816(acc[nb * 2],     aa_h, beh0);
                mma16816(acc[nb * 2 + 1], aa_h, beh1);
            }
        }
    }
    {
        const int cr = warp_m * 16 + (lane >> 2);
#pragma unroll
        for (int fn = 0; fn < 8; fn++) {
            const int dc = warp_n * 64 + fn * 8 + (lane & 3) * 2;
            atomicAdd(&g_sums[cr * DD + dc],           acc[fn][0]);
            atomicAdd(&g_sums[cr * DD + dc + 1],       acc[fn][1]);
            atomicAdd(&g_sums[(cr + 8) * DD + dc],     acc[fn][2]);
            atomicAdd(&g_sums[(cr + 8) * DD + dc + 1], acc[fn][3]);
        }
    }
}

// ---------------- 3c. finalize prototypes (+ re-zero g_sums) ----------------
__global__ __launch_bounds__(128) void k_final() {
    __shared__ float red[128];
    const int c = blockIdx.x, d = threadIdx.x;
    float p = g_sums[c * DD + d] * (1.0f / (float)NTOT);
    g_sums[c * DD + d] = 0.f;
    g_proto[c * DD + d] = p;
    __nv_bfloat16 h, l;
    split1(p, h, l);
    g_ph[c * DD + d] = h;
    g_pl[c * DD + d] = l;
    red[d] = p * p;
    __syncthreads();
    for (int o = 64; o > 0; o >>= 1) {
        if (d < o) red[d] += red[d + o];
        __syncthreads();
    }
    if (d == 0) g_p2[c] = red[0];
}

// ---------------- 4. query logits via mma (full 3-product split) ------------
__global__ __launch_bounds__(256) void k_logits(float* __restrict__ out) {
    extern __shared__ char sm[];
    float* S_sh = (float*)sm;                // [64][65]
    float* e2_s = S_sh + 64 * 65;
    float* p2_s = e2_s + 64;
    __nv_bfloat16* hb = (__nv_bfloat16*)(sm + FP32_BYTES);
    const uint32_t hbase = smem_u32(sm) + FP32_BYTES;

    const int t = threadIdx.x, wid = t >> 5, lane = t & 31;
    const int lr = lane & 15, lc = lane >> 4;
    const int warp_m = wid & 3, warp_n = wid >> 2;

    for (int l = t; l < 64 * 16; l += 256) {
        int r = l >> 4, ch = l & 15;
        *(uint4*)&hb[PH_OFF + r * P_STR + ch * 8] = *(const uint4*)(g_ph + r * DD + ch * 8);
        *(uint4*)&hb[PL_OFF + r * P_STR + ch * 8] = *(const uint4*)(g_pl + r * DD + ch * 8);
    }
    if (t < 64) p2_s[t] = g_p2[t];

    const int q0 = blockIdx.x * 64;
    const int row0 = NS + q0;
    for (int l = t; l < 64 * 16; l += 256) {
        int r = l >> 4, ch = l & 15;
        *(uint4*)&hb[EH_OFF + r * P_STR + ch * 8] =
            *(const uint4*)(g_embh + (size_t)(row0 + r) * DD + ch * 8);
        *(uint4*)&hb[EL_OFF + r * P_STR + ch * 8] =
            *(const uint4*)(g_embl + (size_t)(row0 + r) * DD + ch * 8);
    }
    if (t < 64) e2_s[t] = g_e2[row0 + t];
    __syncthreads();

    float sacc[4][4];
#pragma unroll
    for (int i = 0; i < 4; i++)
#pragma unroll
        for (int j = 0; j < 4; j++) sacc[i][j] = 0.f;
#pragma unroll
    for (int ks = 0; ks < 8; ks++) {
        const int kk = ks * 16;
        uint32_t ah4[4], al4[4];
        ldm_x4(ah4, hbase + 2 * (EH_OFF + (warp_m * 16 + lr) * P_STR + kk + lc * 8));
        ldm_x4(al4, hbase + 2 * (EL_OFF + (warp_m * 16 + lr) * P_STR + kk + lc * 8));
        uint32_t bh[4][2], bl[4][2];
#pragma unroll
        for (int nb = 0; nb < 2; nb++) {
            uint32_t r4[4];
            ldm_x4(r4, hbase + 2 * (PH_OFF + (warp_n * 32 + nb * 16 + lr) * P_STR + kk + lc * 8));
            bh[nb * 2][0] = r4[0]; bh[nb * 2][1] = r4[2];
            bh[nb * 2 + 1][0] = r4[1]; bh[nb * 2 + 1][1] = r4[3];
            ldm_x4(r4, hbase + 2 * (PL_OFF + (warp_n * 32 + nb * 16 + lr) * P_STR + kk + lc * 8));
            bl[nb * 2][0] = r4[0]; bl[nb * 2][1] = r4[2];
            bl[nb * 2 + 1][0] = r4[1]; bl[nb * 2 + 1][1] = r4[3];
        }
#pragma unroll
        for (int fn = 0; fn < 4; fn++) {
            mma16816(sacc[fn], ah4, bh[fn]);
            mma16816(sacc[fn], ah4, bl[fn]);
            mma16816(sacc[fn], al4, bh[fn]);
        }
    }
    {
        const int rr = warp_m * 16 + (lane >> 2);
#pragma unroll
        for (int fn = 0; fn < 4; fn++) {
            const int cc = warp_n * 32 + fn * 8 + (lane & 3) * 2;
            S_sh[rr * 65 + cc] =
                -sqrtf(fmaxf(e2_s[rr] + p2_s[cc] - 2.f * sacc[fn][0], 0.f));
            S_sh[rr * 65 + cc + 1] =
                -sqrtf(fmaxf(e2_s[rr] + p2_s[cc + 1] - 2.f * sacc[fn][1], 0.f));
            S_sh[(rr + 8) * 65 + cc] =
                -sqrtf(fmaxf(e2_s[rr + 8] + p2_s[cc] - 2.f * sacc[fn][2], 0.f));
            S_sh[(rr + 8) * 65 + cc + 1] =
                -sqrtf(fmaxf(e2_s[rr + 8] + p2_s[cc + 1] - 2.f * sacc[fn][3], 0.f));
        }
    }
    __syncthreads();
    for (int l = t; l < 64 * CC; l += 256) {
        int r = l >> 6, c = l & 63;
        out[(size_t)(q0 + r) * CC + c] = S_sh[r * 65 + c];
    }
}

// ---------------- launch ----------------------------------------------------
extern "C" void kernel_launch(void* const* d_in, const int* in_sizes, int n_in,
                              void* d_out, int out_size) {
    const float* sup = (const float*)d_in[0];
    const float* qry = (const float*)d_in[1];
    const int*   lab = (const int*)d_in[2];
    const float* W   = (const float*)d_in[3];
    const float* b   = (const float*)d_in[4];
    float* out = (float*)d_out;

    cudaFuncSetAttribute(k_prop,   cudaFuncAttributeMaxDynamicSharedMemorySize, PROP_SMEM);
    cudaFuncSetAttribute(k_logits, cudaFuncAttributeMaxDynamicSharedMemorySize, LOG_SMEM);
    cudaFuncSetAttribute(k_embed_mma, cudaFuncAttributeMaxDynamicSharedMemorySize, EMB_SMEM_BYTES);
    cudaFuncSetAttribute(k_prop,   cudaFuncAttributePreferredSharedMemoryCarveout, 100);
    cudaFuncSetAttribute(k_logits, cudaFuncAttributePreferredSharedMemoryCarveout, 100);
    cudaFuncSetAttribute(k_embed_mma, cudaFuncAttributePreferredSharedMemoryCarveout, 100);

    k_wconv<<<64, 1024>>>(W);
    k_embed_mma<<<MTILES, 512, EMB_SMEM_BYTES>>>(sup, qry, b);
    k_init<<<CC, 128>>>(lab);
    for (int it = 0; it < 3; it++) {
        k_prop<<<PROP_GRID, 256, PROP_SMEM>>>();
        k_final<<<CC, 128>>>();
    }
    k_logits<<<QTILES, 256, LOG_SMEM>>>(out);
}

// round 13
// speedup vs baseline: 1.0621x; 1.0621x over previous
#include <cuda_runtime.h>
#include <cuda_bf16.h>
#include <math.h>
#include <stdint.h>

#define NS    3200
#define NQ    200000
#define NTOT  203200        // NS + NQ
#define INF_  512
#define DD    128
#define CC    64
#define NTILES   (NTOT/64)  // 3175
#define QTILES   (NQ/64)    // 3125
#define MTILES   ((NTOT + 127) / 128)   // 1588

// ---------------- scratch (device globals; no allocation allowed) ----------
__device__ float g_embS[(size_t)NS * DD];        // fp32 support embeddings
__device__ __nv_bfloat16 g_embh[(size_t)NTOT * DD];  // emb hi
__device__ __nv_bfloat16 g_embl[(size_t)NTOT * DD];  // emb lo
__device__ float g_e2[NTOT];                 // per-row squared norms
__device__ float g_proto[CC * DD];           // prototypes fp32 [64][128]
__device__ __nv_bfloat16 g_ph[CC * DD];      // proto hi
__device__ __nv_bfloat16 g_pl[CC * DD];      // proto lo
__device__ float g_p2[CC];                   // proto squared norms
__device__ float g_sums[CC * DD];            // accumulation buffer
__device__ __nv_bfloat16 g_whi[INF_ * DD];   // W hi  [512][128]
__device__ __nv_bfloat16 g_wlo[INF_ * DD];   // W lo  [512][128]

// ================= helpers ==================================================
__device__ __forceinline__ uint32_t smem_u32(const void* p) {
    uint32_t a;
    asm("{ .reg .u64 t; cvta.to.shared.u64 t, %1; cvt.u32.u64 %0, t; }"
        : "=r"(a) : "l"(p));
    return a;
}
__device__ __forceinline__ void mma16816(float* d, const uint32_t* a, const uint32_t* b) {
    asm volatile(
        "mma.sync.aligned.m16n8k16.row.col.f32.bf16.bf16.f32 "
        "{%0,%1,%2,%3}, {%4,%5,%6,%7}, {%8,%9}, {%0,%1,%2,%3};\n"
        : "+f"(d[0]), "+f"(d[1]), "+f"(d[2]), "+f"(d[3])
        : "r"(a[0]), "r"(a[1]), "r"(a[2]), "r"(a[3]), "r"(b[0]), "r"(b[1]));
}
__device__ __forceinline__ void ldm_x4(uint32_t* r, uint32_t addr) {
    asm volatile("ldmatrix.sync.aligned.m8n8.x4.shared.b16 {%0,%1,%2,%3}, [%4];\n"
                 : "=r"(r[0]), "=r"(r[1]), "=r"(r[2]), "=r"(r[3]) : "r"(addr));
}
__device__ __forceinline__ void ldm_x4_t(uint32_t* r, uint32_t addr) {
    asm volatile("ldmatrix.sync.aligned.m8n8.x4.trans.shared.b16 {%0,%1,%2,%3}, [%4];\n"
                 : "=r"(r[0]), "=r"(r[1]), "=r"(r[2]), "=r"(r[3]) : "r"(addr));
}
__device__ __forceinline__ uint32_t pack2(__nv_bfloat16 a, __nv_bfloat16 b) {
    return ((uint32_t)__bfloat16_as_ushort(b) << 16) | (uint32_t)__bfloat16_as_ushort(a);
}
__device__ __forceinline__ void split1(float x, __nv_bfloat16& h, __nv_bfloat16& l) {
    h = __float2bfloat16_rn(x);
    l = __float2bfloat16_rn(x - __bfloat162float(h));
}

// ---------------- 0. W convert (hi/lo split, natural [K][N] layout) ---------
__global__ void k_wconv(const float* __restrict__ W) {
    int i = blockIdx.x * blockDim.x + threadIdx.x;
    if (i < INF_ * DD) {
        __nv_bfloat16 h, l;
        split1(W[i], h, l);
        g_whi[i] = h;
        g_wlo[i] = l;
    }
}

// ---------------- 1. embedding GEMM via mma.sync bf16 (fp32-split) ----------
// EXACT R6 structure (measured best of 5 variants): 256 threads, split at STS,
// single buffer, ldmatrix A+B.
#define A_STR 72
#define B_STR 136
#define AHI_OFF 0
#define ALO_OFF (128 * A_STR)
#define BHI_OFF (2 * 128 * A_STR)
#define BLO_OFF (BHI_OFF + 64 * B_STR)
#define EMB_SMEM_HALVES (BLO_OFF + 64 * B_STR)
#define EMB_SMEM_BYTES  (EMB_SMEM_HALVES * 2)   // 71680
#define C_STR 132

__global__ __launch_bounds__(256)
void k_embed_mma(const float* __restrict__ sup, const float* __restrict__ qry,
                 const float* __restrict__ bias) {
    extern __shared__ char smraw[];
    __nv_bfloat16* sh = (__nv_bfloat16*)smraw;
    float* shf = (float*)smraw;
    const uint32_t sbase = smem_u32(smraw);

    const int t = threadIdx.x;
    const int wid = t >> 5, lane = t & 31;
    const int warp_m = wid & 3;
    const int warp_n = wid >> 2;
    const int m0 = blockIdx.x * 128;
    const int lr = lane & 15;
    const int lc = lane >> 4;

    float acc[2][8][4];
#pragma unroll
    for (int i = 0; i < 2; i++)
#pragma unroll
        for (int j = 0; j < 8; j++)
#pragma unroll
            for (int q = 0; q < 4; q++) acc[i][j][q] = 0.f;

    for (int kb = 0; kb < 8; kb++) {
        const int k0 = kb * 64;
        __syncthreads();
#pragma unroll
        for (int p = 0; p < 8; p++) {
            int l = t + 256 * p;
            int r = l >> 4, q = l & 15;
            int row = m0 + r;
            if (row >= NTOT) row = NTOT - 1;
            const float* src = (row < NS) ? (sup + (size_t)row * INF_)
                                          : (qry + (size_t)(row - NS) * INF_);
            float4 v = *(const float4*)(src + k0 + q * 4);
            __nv_bfloat16 h0, l0, h1, l1, h2, l2, h3, l3;
            split1(v.x, h0, l0); split1(v.y, h1, l1);
            split1(v.z, h2, l2); split1(v.w, h3, l3);
            *(uint2*)&sh[AHI_OFF + r * A_STR + q * 4] =
                make_uint2(pack2(h0, h1), pack2(h2, h3));
            *(uint2*)&sh[ALO_OFF + r * A_STR + q * 4] =
                make_uint2(pack2(l0, l1), pack2(l2, l3));
        }
#pragma unroll
        for (int p = 0; p < 4; p++) {
            int l = t + 256 * p;
            int kr = l >> 4, ch = l & 15;
            *(uint4*)&sh[BHI_OFF + kr * B_STR + ch * 8] =
                *(const uint4*)(g_whi + (size_t)(k0 + kr) * DD + ch * 8);
            *(uint4*)&sh[BLO_OFF + kr * B_STR + ch * 8] =
                *(const uint4*)(g_wlo + (size_t)(k0 + kr) * DD + ch * 8);
        }
        __syncthreads();

#pragma unroll
        for (int ks = 0; ks < 4; ks++) {
            const int kk = ks * 16;
            uint32_t bh[8][2], bl[8][2];
#pragma unroll
            for (int nb = 0; nb < 4; nb++) {
                uint32_t r4[4];
                uint32_t addr = sbase + 2 * (BHI_OFF + (kk + lr) * B_STR
                                 + warp_n * 64 + nb * 16 + lc * 8);
                ldm_x4_t(r4, addr);
                bh[nb * 2][0] = r4[0]; bh[nb * 2][1] = r4[1];
                bh[nb * 2 + 1][0] = r4[2]; bh[nb * 2 + 1][1] = r4[3];
                addr = sbase + 2 * (BLO_OFF + (kk + lr) * B_STR
                                 + warp_n * 64 + nb * 16 + lc * 8);
                ldm_x4_t(r4, addr);
                bl[nb * 2][0] = r4[0]; bl[nb * 2][1] = r4[1];
                bl[nb * 2 + 1][0] = r4[2]; bl[nb * 2 + 1][1] = r4[3];
            }
#pragma unroll
            for (int fm = 0; fm < 2; fm++) {
                uint32_t ah[4], al[4];
                int arow = warp_m * 32 + fm * 16 + lr;
                ldm_x4(ah, sbase + 2 * (AHI_OFF + arow * A_STR + kk + lc * 8));
                ldm_x4(al, sbase + 2 * (ALO_OFF + arow * A_STR + kk + lc * 8));
#pragma unroll
                for (int fn = 0; fn < 8; fn++) {
                    mma16816(acc[fm][fn], ah, bh[fn]);
                    mma16816(acc[fm][fn], ah, bl[fn]);
                    mma16816(acc[fm][fn], al, bh[fn]);
                }
            }
        }
    }

    // ---- epilogue ----
    __syncthreads();
#pragma unroll
    for (int fm = 0; fm < 2; fm++)
#pragma unroll
        for (int fn = 0; fn < 8; fn++) {
            int r0 = warp_m * 32 + fm * 16 + (lane >> 2);
            int c0 = warp_n * 64 + fn * 8 + (lane & 3) * 2;
            shf[r0 * C_STR + c0]           = acc[fm][fn][0];
            shf[r0 * C_STR + c0 + 1]       = acc[fm][fn][1];
            shf[(r0 + 8) * C_STR + c0]     = acc[fm][fn][2];
            shf[(r0 + 8) * C_STR + c0 + 1] = acc[fm][fn][3];
        }
    __syncthreads();
    {
        const int r = t >> 1, half = t & 1;
        const int row = m0 + r;
        float e2 = 0.f;
        if (row < NTOT) {
            const float* srow = &shf[r * C_STR + half * 64];
            __nv_bfloat16* dh = g_embh + (size_t)row * DD + half * 64;
            __nv_bfloat16* dl = g_embl + (size_t)row * DD + half * 64;
#pragma unroll
            for (int j = 0; j < 64; j += 4) {
                float4 o;
                o.x = srow[j + 0] + __ldg(bias + half * 64 + j + 0);
                o.y = srow[j + 1] + __ldg(bias + half * 64 + j + 1);
                o.z = srow[j + 2] + __ldg(bias + half * 64 + j + 2);
                o.w = srow[j + 3] + __ldg(bias + half * 64 + j + 3);
                if (row < NS)
                    *(float4*)(g_embS + (size_t)row * DD + half * 64 + j) = o;
                __nv_bfloat16 h0, l0, h1, l1, h2, l2, h3, l3;
                split1(o.x, h0, l0); split1(o.y, h1, l1);
                split1(o.z, h2, l2); split1(o.w, h3, l3);
                *(uint2*)(dh + j) = make_uint2(pack2(h0, h1), pack2(h2, h3));
                *(uint2*)(dl + j) = make_uint2(pack2(l0, l1), pack2(l2, l3));
                e2 += o.x * o.x + o.y * o.y + o.z * o.z + o.w * o.w;
            }
        }
        float e2o = __shfl_xor_sync(0xffffffffu, e2, 1);
        if (half == 0 && row < NTOT) g_e2[row] = e2 + e2o;
    }
}

// ---------------- 2. initial prototypes: segment mean (+ zero g_sums) ------
__global__ __launch_bounds__(128) void k_init(const int* __restrict__ lab) {
    __shared__ float red[128];
    const int c = blockIdx.x, d = threadIdx.x;
    g_sums[c * DD + d] = 0.f;
    float sum = 0.f; int cnt = 0;
    for (int n = 0; n < NS; n++) {
        if (__ldg(&lab[n]) == c) { sum += g_embS[(size_t)n * DD + d]; cnt++; }
    }
    float p = sum / fmaxf((float)cnt, 1.0f);
    g_proto[c * DD + d] = p;
    __nv_bfloat16 h, l;
    split1(p, h, l);
    g_ph[c * DD + d] = h;
    g_pl[c * DD + d] = l;
    red[d] = p * p;
    __syncthreads();
    for (int o = 64; o > 0; o >>= 1) {
        if (d < o) red[d] += red[d + o];
        __syncthreads();
    }
    if (d == 0) g_p2[c] = red[0];
}

// ---------------- 3b. fused attention + prototype accumulation (mma) -------
// HI-ONLY in-loop precision. AH overlays the S_sh region (S_sh dead after the
// softmax register read; extra barrier makes the alias safe) -> 51968 B smem
// -> 4 CTAs/SM.
#define FP32_BYTES 17152
#define PAH_OFF 0                      // halves; overlays S_sh bytes [0,9216)
#define PPH_OFF (17152 / 2)            // 8576 halves
#define PEH_OFF (PPH_OFF + 64 * 136)   // 17280 halves
#define PROP_SMEM (17152 + 2 * 64 * 136 * 2)   // 51968
#define P_STR 136
#define AT_STR 72
#define PH_OFF 0
#define PL_OFF 8704
#define EH_OFF 17408
#define EL_OFF 26112
#define LOG_SMEM (FP32_BYTES + 34816 * 2)      // 86784
#define PROP_GRID 592

__global__ __launch_bounds__(256) void k_prop() {
    extern __shared__ char sm[];
    float* S_sh = (float*)sm;                // [64][65] (aliased by AH later)
    float* e2_s = S_sh + 64 * 65;            // bytes 16640..16896
    float* p2_s = e2_s + 64;                 // bytes 16896..17152
    __nv_bfloat16* hb = (__nv_bfloat16*)sm;  // half-indexed from base
    const uint32_t hbase = smem_u32(sm);

    const int t = threadIdx.x, wid = t >> 5, lane = t & 31;
    const int lr = lane & 15, lc = lane >> 4;
    const int warp_m = wid & 3, warp_n = wid >> 2;

    for (int l = t; l < 64 * 16; l += 256) {
        int r = l >> 4, ch = l & 15;
        *(uint4*)&hb[PPH_OFF + r * P_STR + ch * 8] = *(const uint4*)(g_ph + r * DD + ch * 8);
    }
    if (t < 64) p2_s[t] = g_p2[t];

    float acc[8][4];
#pragma unroll
    for (int j = 0; j < 8; j++)
#pragma unroll
        for (int q = 0; q < 4; q++) acc[j][q] = 0.f;

    for (int tile = blockIdx.x; tile < NTILES; tile += gridDim.x) {
        const int row0 = tile * 64;
        __syncthreads();     // prev iter's GEMM2 (AH + EH reads) complete
        for (int l = t; l < 64 * 16; l += 256) {
            int r = l >> 4, ch = l & 15;
            *(uint4*)&hb[PEH_OFF + r * P_STR + ch * 8] =
                *(const uint4*)(g_embh + (size_t)(row0 + r) * DD + ch * 8);
        }
        if (t < 64) e2_s[t] = g_e2[row0 + t];
        __syncthreads();

        // ---- GEMM1 (hi x hi): S = emb @ proto^T ----
        float sacc[4][4];
#pragma unroll
        for (int i = 0; i < 4; i++)
#pragma unroll
            for (int j = 0; j < 4; j++) sacc[i][j] = 0.f;
#pragma unroll
        for (int ks = 0; ks < 8; ks++) {
            const int kk = ks * 16;
            uint32_t ah4[4];
            ldm_x4(ah4, hbase + 2 * (PEH_OFF + (warp_m * 16 + lr) * P_STR + kk + lc * 8));
            uint32_t bh[4][2];
#pragma unroll
            for (int nb = 0; nb < 2; nb++) {
                uint32_t r4[4];
                ldm_x4(r4, hbase + 2 * (PPH_OFF + (warp_n * 32 + nb * 16 + lr) * P_STR + kk + lc * 8));
                bh[nb * 2][0] = r4[0]; bh[nb * 2][1] = r4[2];
                bh[nb * 2 + 1][0] = r4[1]; bh[nb * 2 + 1][1] = r4[3];
            }
#pragma unroll
            for (int fn = 0; fn < 4; fn++)
                mma16816(sacc[fn], ah4, bh[fn]);
        }
        {
            const int rr = warp_m * 16 + (lane >> 2);
#pragma unroll
            for (int fn = 0; fn < 4; fn++) {
                const int cc = warp_n * 32 + fn * 8 + (lane & 3) * 2;
                S_sh[rr * 65 + cc] =
                    sqrtf(fmaxf(e2_s[rr] + p2_s[cc] - 2.f * sacc[fn][0], 0.f));
                S_sh[rr * 65 + cc + 1] =
                    sqrtf(fmaxf(e2_s[rr] + p2_s[cc + 1] - 2.f * sacc[fn][1], 0.f));
                S_sh[(rr + 8) * 65 + cc] =
                    sqrtf(fmaxf(e2_s[rr + 8] + p2_s[cc] - 2.f * sacc[fn][2], 0.f));
                S_sh[(rr + 8) * 65 + cc + 1] =
                    sqrtf(fmaxf(e2_s[rr + 8] + p2_s[cc + 1] - 2.f * sacc[fn][3], 0.f));
            }
        }
        __syncthreads();

        // ---- softmax: read S into regs, barrier, write AH (aliases S_sh) ----
        {
            const int r = t >> 2, sg = t & 3;
            const int cbase = sg * 16;
            float mn = 1e30f;
#pragma unroll
            for (int i = 0; i < 16; i++) mn = fminf(mn, S_sh[r * 65 + cbase + i]);
            mn = fminf(mn, __shfl_xor_sync(0xffffffffu, mn, 1));
            mn = fminf(mn, __shfl_xor_sync(0xffffffffu, mn, 2));
            float w[16];
            float s = 0.f;
#pragma unroll
            for (int i = 0; i < 16; i++) {
                w[i] = __expf(mn - S_sh[r * 65 + cbase + i]);
                s += w[i];
            }
            s += __shfl_xor_sync(0xffffffffu, s, 1);
            s += __shfl_xor_sync(0xffffffffu, s, 2);
            const float inv = 1.0f / s;
            __syncthreads();   // all S_sh reads done before AH overlay writes
#pragma unroll
            for (int i = 0; i < 16; i += 2)
                *(uint32_t*)&hb[PAH_OFF + r * AT_STR + cbase + i] =
                    pack2(__float2bfloat16_rn(w[i] * inv),
                          __float2bfloat16_rn(w[i + 1] * inv));
        }
        __syncthreads();

        // ---- GEMM2 (hi x hi): acc += attn^T @ emb ----
#pragma unroll
        for (int ks = 0; ks < 4; ks++) {
            const int kk = ks * 16;
            uint32_t r4[4];
            uint32_t aa_h[4];
            ldm_x4_t(r4, hbase + 2 * (PAH_OFF + (kk + lr) * AT_STR + warp_m * 16 + lc * 8));
            aa_h[0] = r4[0]; aa_h[1] = r4[2]; aa_h[2] = r4[1]; aa_h[3] = r4[3];
#pragma unroll
            for (int nb = 0; nb < 4; nb++) {
                uint32_t e4[4];
                uint32_t beh0[2], beh1[2];
                ldm_x4_t(e4, hbase + 2 * (PEH_OFF + (kk + lr) * P_STR + warp_n * 64 + nb * 16 + lc * 8));
                beh0[0] = e4[0]; beh0[1] = e4[1];
                beh1[0] = e4[2]; beh1[1] = e4[3];
                mma16816(acc[nb * 2],     aa_h, beh0);
                mma16816(acc[nb * 2 + 1], aa_h, beh1);
            }
        }
    }
    {
        const int cr = warp_m * 16 + (lane >> 2);
#pragma unroll
        for (int fn = 0; fn < 8; fn++) {
            const int dc = warp_n * 64 + fn * 8 + (lane & 3) * 2;
            atomicAdd(&g_sums[cr * DD + dc],           acc[fn][0]);
            atomicAdd(&g_sums[cr * DD + dc + 1],       acc[fn][1]);
            atomicAdd(&g_sums[(cr + 8) * DD + dc],     acc[fn][2]);
            atomicAdd(&g_sums[(cr + 8) * DD + dc + 1], acc[fn][3]);
        }
    }
}

// ---------------- 3c. finalize prototypes (+ re-zero g_sums) ----------------
__global__ __launch_bounds__(128) void k_final() {
    __shared__ float red[128];
    const int c = blockIdx.x, d = threadIdx.x;
    float p = g_sums[c * DD + d] * (1.0f / (float)NTOT);
    g_sums[c * DD + d] = 0.f;
    g_proto[c * DD + d] = p;
    __nv_bfloat16 h, l;
    split1(p, h, l);
    g_ph[c * DD + d] = h;
    g_pl[c * DD + d] = l;
    red[d] = p * p;
    __syncthreads();
    for (int o = 64; o > 0; o >>= 1) {
        if (d < o) red[d] += red[d + o];
        __syncthreads();
    }
    if (d == 0) g_p2[c] = red[0];
}

// ---------------- 4. query logits via mma (full 3-product split) ------------
__global__ __launch_bounds__(256) void k_logits(float* __restrict__ out) {
    extern __shared__ char sm[];
    float* S_sh = (float*)sm;                // [64][65]
    float* e2_s = S_sh + 64 * 65;
    float* p2_s = e2_s + 64;
    __nv_bfloat16* hb = (__nv_bfloat16*)(sm + FP32_BYTES);
    const uint32_t hbase = smem_u32(sm) + FP32_BYTES;

    const int t = threadIdx.x, wid = t >> 5, lane = t & 31;
    const int lr = lane & 15, lc = lane >> 4;
    const int warp_m = wid & 3, warp_n = wid >> 2;

    for (int l = t; l < 64 * 16; l += 256) {
        int r = l >> 4, ch = l & 15;
        *(uint4*)&hb[PH_OFF + r * P_STR + ch * 8] = *(const uint4*)(g_ph + r * DD + ch * 8);
        *(uint4*)&hb[PL_OFF + r * P_STR + ch * 8] = *(const uint4*)(g_pl + r * DD + ch * 8);
    }
    if (t < 64) p2_s[t] = g_p2[t];

    const int q0 = blockIdx.x * 64;
    const int row0 = NS + q0;
    for (int l = t; l < 64 * 16; l += 256) {
        int r = l >> 4, ch = l & 15;
        *(uint4*)&hb[EH_OFF + r * P_STR + ch * 8] =
            *(const uint4*)(g_embh + (size_t)(row0 + r) * DD + ch * 8);
        *(uint4*)&hb[EL_OFF + r * P_STR + ch * 8] =
            *(const uint4*)(g_embl + (size_t)(row0 + r) * DD + ch * 8);
    }
    if (t < 64) e2_s[t] = g_e2[row0 + t];
    __syncthreads();

    float sacc[4][4];
#pragma unroll
    for (int i = 0; i < 4; i++)
#pragma unroll
        for (int j = 0; j < 4; j++) sacc[i][j] = 0.f;
#pragma unroll
    for (int ks = 0; ks < 8; ks++) {
        const int kk = ks * 16;
        uint32_t ah4[4], al4[4];
        ldm_x4(ah4, hbase + 2 * (EH_OFF + (warp_m * 16 + lr) * P_STR + kk + lc * 8));
        ldm_x4(al4, hbase + 2 * (EL_OFF + (warp_m * 16 + lr) * P_STR + kk + lc * 8));
        uint32_t bh[4][2], bl[4][2];
#pragma unroll
        for (int nb = 0; nb < 2; nb++) {
            uint32_t r4[4];
            ldm_x4(r4, hbase + 2 * (PH_OFF + (warp_n * 32 + nb * 16 + lr) * P_STR + kk + lc * 8));
            bh[nb * 2][0] = r4[0]; bh[nb * 2][1] = r4[2];
            bh[nb * 2 + 1][0] = r4[1]; bh[nb * 2 + 1][1] = r4[3];
            ldm_x4(r4, hbase + 2 * (PL_OFF + (warp_n * 32 + nb * 16 + lr) * P_STR + kk + lc * 8));
            bl[nb * 2][0] = r4[0]; bl[nb * 2][1] = r4[2];
            bl[nb * 2 + 1][0] = r4[1]; bl[nb * 2 + 1][1] = r4[3];
        }
#pragma unroll
        for (int fn = 0; fn < 4; fn++) {
            mma16816(sacc[fn], ah4, bh[fn]);
            mma16816(sacc[fn], ah4, bl[fn]);
            mma16816(sacc[fn], al4, bh[fn]);
        }
    }
    {
        const int rr = warp_m * 16 + (lane >> 2);
#pragma unroll
        for (int fn = 0; fn < 4; fn++) {
            const int cc = warp_n * 32 + fn * 8 + (lane & 3) * 2;
            S_sh[rr * 65 + cc] =
                -sqrtf(fmaxf(e2_s[rr] + p2_s[cc] - 2.f * sacc[fn][0], 0.f));
            S_sh[rr * 65 + cc + 1] =
                -sqrtf(fmaxf(e2_s[rr] + p2_s[cc + 1] - 2.f * sacc[fn][1], 0.f));
            S_sh[(rr + 8) * 65 + cc] =
                -sqrtf(fmaxf(e2_s[rr + 8] + p2_s[cc] - 2.f * sacc[fn][2], 0.f));
            S_sh[(rr + 8) * 65 + cc + 1] =
                -sqrtf(fmaxf(e2_s[rr + 8] + p2_s[cc + 1] - 2.f * sacc[fn][3], 0.f));
        }
    }
    __syncthreads();
    for (int l = t; l < 64 * CC; l += 256) {
        int r = l >> 6, c = l & 63;
        out[(size_t)(q0 + r) * CC + c] = S_sh[r * 65 + c];
    }
}

// ---------------- launch ----------------------------------------------------
extern "C" void kernel_launch(void* const* d_in, const int* in_sizes, int n_in,
                              void* d_out, int out_size) {
    const float* sup = (const float*)d_in[0];
    const float* qry = (const float*)d_in[1];
    const int*   lab = (const int*)d_in[2];
    const float* W   = (const float*)d_in[3];
    const float* b   = (const float*)d_in[4];
    float* out = (float*)d_out;

    cudaFuncSetAttribute(k_prop,   cudaFuncAttributeMaxDynamicSharedMemorySize, PROP_SMEM);
    cudaFuncSetAttribute(k_logits, cudaFuncAttributeMaxDynamicSharedMemorySize, LOG_SMEM);
    cudaFuncSetAttribute(k_embed_mma, cudaFuncAttributeMaxDynamicSharedMemorySize, EMB_SMEM_BYTES);
    cudaFuncSetAttribute(k_prop,   cudaFuncAttributePreferredSharedMemoryCarveout, 100);
    cudaFuncSetAttribute(k_logits, cudaFuncAttributePreferredSharedMemoryCarveout, 100);
    cudaFuncSetAttribute(k_embed_mma, cudaFuncAttributePreferredSharedMemoryCarveout, 100);

    k_wconv<<<64, 1024>>>(W);
    k_embed_mma<<<MTILES, 256, EMB_SMEM_BYTES>>>(sup, qry, b);
    k_init<<<CC, 128>>>(lab);
    for (int it = 0; it < 3; it++) {
        k_prop<<<PROP_GRID, 256, PROP_SMEM>>>();
        k_final<<<CC, 128>>>();
    }
    k_logits<<<QTILES, 256, LOG_SMEM>>>(out);
}

// round 14
// speedup vs baseline: 1.1155x; 1.0503x over previous
#include <cuda_runtime.h>
#include <cuda_bf16.h>
#include <math.h>
#include <stdint.h>

#define NS    3200
#define NQ    200000
#define NTOT  203200        // NS + NQ
#define INF_  512
#define DD    128
#define CC    64
#define NTILES   (NTOT/64)  // 3175
#define QTILES   (NQ/64)    // 3125
#define MTILES   ((NTOT + 127) / 128)   // 1588

// ---------------- scratch (device globals; no allocation allowed) ----------
__device__ float g_embS[(size_t)NS * DD];        // fp32 support embeddings
__device__ __nv_bfloat16 g_embh[(size_t)NTOT * DD];  // emb hi
__device__ __nv_bfloat16 g_embl[(size_t)NTOT * DD];  // emb lo
__device__ float g_e2[NTOT];                 // per-row squared norms
__device__ float g_proto[CC * DD];           // prototypes fp32 [64][128]
__device__ __nv_bfloat16 g_ph[CC * DD];      // proto hi
__device__ __nv_bfloat16 g_pl[CC * DD];      // proto lo
__device__ float g_p2[CC];                   // proto squared norms
__device__ float g_sums[CC * DD];            // accumulation buffer
__device__ __nv_bfloat16 g_whi[INF_ * DD];   // W hi  [512][128]
__device__ __nv_bfloat16 g_wlo[INF_ * DD];   // W lo  [512][128]

// ================= helpers ==================================================
__device__ __forceinline__ uint32_t smem_u32(const void* p) {
    uint32_t a;
    asm("{ .reg .u64 t; cvta.to.shared.u64 t, %1; cvt.u32.u64 %0, t; }"
        : "=r"(a) : "l"(p));
    return a;
}
__device__ __forceinline__ void mma16816(float* d, const uint32_t* a, const uint32_t* b) {
    asm volatile(
        "mma.sync.aligned.m16n8k16.row.col.f32.bf16.bf16.f32 "
        "{%0,%1,%2,%3}, {%4,%5,%6,%7}, {%8,%9}, {%0,%1,%2,%3};\n"
        : "+f"(d[0]), "+f"(d[1]), "+f"(d[2]), "+f"(d[3])
        : "r"(a[0]), "r"(a[1]), "r"(a[2]), "r"(a[3]), "r"(b[0]), "r"(b[1]));
}
__device__ __forceinline__ void ldm_x4(uint32_t* r, uint32_t addr) {
    asm volatile("ldmatrix.sync.aligned.m8n8.x4.shared.b16 {%0,%1,%2,%3}, [%4];\n"
                 : "=r"(r[0]), "=r"(r[1]), "=r"(r[2]), "=r"(r[3]) : "r"(addr));
}
__device__ __forceinline__ void ldm_x4_t(uint32_t* r, uint32_t addr) {
    asm volatile("ldmatrix.sync.aligned.m8n8.x4.trans.shared.b16 {%0,%1,%2,%3}, [%4];\n"
                 : "=r"(r[0]), "=r"(r[1]), "=r"(r[2]), "=r"(r[3]) : "r"(addr));
}
__device__ __forceinline__ uint32_t pack2(__nv_bfloat16 a, __nv_bfloat16 b) {
    return ((uint32_t)__bfloat16_as_ushort(b) << 16) | (uint32_t)__bfloat16_as_ushort(a);
}
__device__ __forceinline__ void split1(float x, __nv_bfloat16& h, __nv_bfloat16& l) {
    h = __float2bfloat16_rn(x);
    l = __float2bfloat16_rn(x - __bfloat162float(h));
}

// ---------------- 0. W convert (hi/lo split, natural [K][N] layout) ---------
__global__ void k_wconv(const float* __restrict__ W) {
    int i = blockIdx.x * blockDim.x + threadIdx.x;
    if (i < INF_ * DD) {
        __nv_bfloat16 h, l;
        split1(W[i], h, l);
        g_whi[i] = h;
        g_wlo[i] = l;
    }
}

// ---------------- 1. embedding GEMM via mma.sync bf16 (fp32-split) ----------
// EXACT R6 structure (measured best): 256 threads, split at STS, single buffer.
#define A_STR 72
#define B_STR 136
#define AHI_OFF 0
#define ALO_OFF (128 * A_STR)
#define BHI_OFF (2 * 128 * A_STR)
#define BLO_OFF (BHI_OFF + 64 * B_STR)
#define EMB_SMEM_HALVES (BLO_OFF + 64 * B_STR)
#define EMB_SMEM_BYTES  (EMB_SMEM_HALVES * 2)   // 71680
#define C_STR 132

__global__ __launch_bounds__(256)
void k_embed_mma(const float* __restrict__ sup, const float* __restrict__ qry,
                 const float* __restrict__ bias) {
    extern __shared__ char smraw[];
    __nv_bfloat16* sh = (__nv_bfloat16*)smraw;
    float* shf = (float*)smraw;
    const uint32_t sbase = smem_u32(smraw);

    const int t = threadIdx.x;
    const int wid = t >> 5, lane = t & 31;
    const int warp_m = wid & 3;
    const int warp_n = wid >> 2;
    const int m0 = blockIdx.x * 128;
    const int lr = lane & 15;
    const int lc = lane >> 4;

    float acc[2][8][4];
#pragma unroll
    for (int i = 0; i < 2; i++)
#pragma unroll
        for (int j = 0; j < 8; j++)
#pragma unroll
            for (int q = 0; q < 4; q++) acc[i][j][q] = 0.f;

    for (int kb = 0; kb < 8; kb++) {
        const int k0 = kb * 64;
        __syncthreads();
#pragma unroll
        for (int p = 0; p < 8; p++) {
            int l = t + 256 * p;
            int r = l >> 4, q = l & 15;
            int row = m0 + r;
            if (row >= NTOT) row = NTOT - 1;
            const float* src = (row < NS) ? (sup + (size_t)row * INF_)
                                          : (qry + (size_t)(row - NS) * INF_);
            float4 v = *(const float4*)(src + k0 + q * 4);
            __nv_bfloat16 h0, l0, h1, l1, h2, l2, h3, l3;
            split1(v.x, h0, l0); split1(v.y, h1, l1);
            split1(v.z, h2, l2); split1(v.w, h3, l3);
            *(uint2*)&sh[AHI_OFF + r * A_STR + q * 4] =
                make_uint2(pack2(h0, h1), pack2(h2, h3));
            *(uint2*)&sh[ALO_OFF + r * A_STR + q * 4] =
                make_uint2(pack2(l0, l1), pack2(l2, l3));
        }
#pragma unroll
        for (int p = 0; p < 4; p++) {
            int l = t + 256 * p;
            int kr = l >> 4, ch = l & 15;
            *(uint4*)&sh[BHI_OFF + kr * B_STR + ch * 8] =
                *(const uint4*)(g_whi + (size_t)(k0 + kr) * DD + ch * 8);
            *(uint4*)&sh[BLO_OFF + kr * B_STR + ch * 8] =
                *(const uint4*)(g_wlo + (size_t)(k0 + kr) * DD + ch * 8);
        }
        __syncthreads();

#pragma unroll
        for (int ks = 0; ks < 4; ks++) {
            const int kk = ks * 16;
            uint32_t bh[8][2], bl[8][2];
#pragma unroll
            for (int nb = 0; nb < 4; nb++) {
                uint32_t r4[4];
                uint32_t addr = sbase + 2 * (BHI_OFF + (kk + lr) * B_STR
                                 + warp_n * 64 + nb * 16 + lc * 8);
                ldm_x4_t(r4, addr);
                bh[nb * 2][0] = r4[0]; bh[nb * 2][1] = r4[1];
                bh[nb * 2 + 1][0] = r4[2]; bh[nb * 2 + 1][1] = r4[3];
                addr = sbase + 2 * (BLO_OFF + (kk + lr) * B_STR
                                 + warp_n * 64 + nb * 16 + lc * 8);
                ldm_x4_t(r4, addr);
                bl[nb * 2][0] = r4[0]; bl[nb * 2][1] = r4[1];
                bl[nb * 2 + 1][0] = r4[2]; bl[nb * 2 + 1][1] = r4[3];
            }
#pragma unroll
            for (int fm = 0; fm < 2; fm++) {
                uint32_t ah[4], al[4];
                int arow = warp_m * 32 + fm * 16 + lr;
                ldm_x4(ah, sbase + 2 * (AHI_OFF + arow * A_STR + kk + lc * 8));
                ldm_x4(al, sbase + 2 * (ALO_OFF + arow * A_STR + kk + lc * 8));
#pragma unroll
                for (int fn = 0; fn < 8; fn++) {
                    mma16816(acc[fm][fn], ah, bh[fn]);
                    mma16816(acc[fm][fn], ah, bl[fn]);
                    mma16816(acc[fm][fn], al, bh[fn]);
                }
            }
        }
    }

    // ---- epilogue ----
    __syncthreads();
#pragma unroll
    for (int fm = 0; fm < 2; fm++)
#pragma unroll
        for (int fn = 0; fn < 8; fn++) {
            int r0 = warp_m * 32 + fm * 16 + (lane >> 2);
            int c0 = warp_n * 64 + fn * 8 + (lane & 3) * 2;
            shf[r0 * C_STR + c0]           = acc[fm][fn][0];
            shf[r0 * C_STR + c0 + 1]       = acc[fm][fn][1];
            shf[(r0 + 8) * C_STR + c0]     = acc[fm][fn][2];
            shf[(r0 + 8) * C_STR + c0 + 1] = acc[fm][fn][3];
        }
    __syncthreads();
    {
        const int r = t >> 1, half = t & 1;
        const int row = m0 + r;
        float e2 = 0.f;
        if (row < NTOT) {
            const float* srow = &shf[r * C_STR + half * 64];
            __nv_bfloat16* dh = g_embh + (size_t)row * DD + half * 64;
            __nv_bfloat16* dl = g_embl + (size_t)row * DD + half * 64;
#pragma unroll
            for (int j = 0; j < 64; j += 4) {
                float4 o;
                o.x = srow[j + 0] + __ldg(bias + half * 64 + j + 0);
                o.y = srow[j + 1] + __ldg(bias + half * 64 + j + 1);
                o.z = srow[j + 2] + __ldg(bias + half * 64 + j + 2);
                o.w = srow[j + 3] + __ldg(bias + half * 64 + j + 3);
                if (row < NS)
                    *(float4*)(g_embS + (size_t)row * DD + half * 64 + j) = o;
                __nv_bfloat16 h0, l0, h1, l1, h2, l2, h3, l3;
                split1(o.x, h0, l0); split1(o.y, h1, l1);
                split1(o.z, h2, l2); split1(o.w, h3, l3);
                *(uint2*)(dh + j) = make_uint2(pack2(h0, h1), pack2(h2, h3));
                *(uint2*)(dl + j) = make_uint2(pack2(l0, l1), pack2(l2, l3));
                e2 += o.x * o.x + o.y * o.y + o.z * o.z + o.w * o.w;
            }
        }
        float e2o = __shfl_xor_sync(0xffffffffu, e2, 1);
        if (half == 0 && row < NTOT) g_e2[row] = e2 + e2o;
    }
}

// ---------------- 2. initial prototypes: segment mean (+ zero g_sums) ------
__global__ __launch_bounds__(128) void k_init(const int* __restrict__ lab) {
    __shared__ float red[128];
    const int c = blockIdx.x, d = threadIdx.x;
    g_sums[c * DD + d] = 0.f;
    float sum = 0.f; int cnt = 0;
    for (int n = 0; n < NS; n++) {
        if (__ldg(&lab[n]) == c) { sum += g_embS[(size_t)n * DD + d]; cnt++; }
    }
    float p = sum / fmaxf((float)cnt, 1.0f);
    g_proto[c * DD + d] = p;
    __nv_bfloat16 h, l;
    split1(p, h, l);
    g_ph[c * DD + d] = h;
    g_pl[c * DD + d] = l;
    red[d] = p * p;
    __syncthreads();
    for (int o = 64; o > 0; o >>= 1) {
        if (d < o) red[d] += red[d + o];
        __syncthreads();
    }
    if (d == 0) g_p2[c] = red[0];
}

// ---------------- 3b. fused attention + prototype accumulation (mma) -------
// R10/R11-proven config: HI-ONLY, separate AH buffer, 61184 B smem, grid 444
// (3 CTAs/SM — register-limited; one clean wave).
#define FP32_BYTES 17152
#define PPH_OFF 0
#define PEH_OFF 8704
#define PAH_OFF 17408
#define PROP_SMEM (FP32_BYTES + (17408 + 64 * 72) * 2)   // 61184
#define P_STR 136
#define AT_STR 72
#define PH_OFF 0
#define PL_OFF 8704
#define EH_OFF 17408
#define EL_OFF 26112
#define LOG_SMEM (FP32_BYTES + 34816 * 2)                // 86784
#define PROP_GRID 444

__global__ __launch_bounds__(256) void k_prop() {
    extern __shared__ char sm[];
    float* S_sh = (float*)sm;                // [64][65]
    float* e2_s = S_sh + 64 * 65;
    float* p2_s = e2_s + 64;
    __nv_bfloat16* hb = (__nv_bfloat16*)(sm + FP32_BYTES);
    const uint32_t hbase = smem_u32(sm) + FP32_BYTES;

    const int t = threadIdx.x, wid = t >> 5, lane = t & 31;
    const int lr = lane & 15, lc = lane >> 4;
    const int warp_m = wid & 3, warp_n = wid >> 2;

    for (int l = t; l < 64 * 16; l += 256) {
        int r = l >> 4, ch = l & 15;
        *(uint4*)&hb[PPH_OFF + r * P_STR + ch * 8] = *(const uint4*)(g_ph + r * DD + ch * 8);
    }
    if (t < 64) p2_s[t] = g_p2[t];

    float acc[8][4];
#pragma unroll
    for (int j = 0; j < 8; j++)
#pragma unroll
        for (int q = 0; q < 4; q++) acc[j][q] = 0.f;

    for (int tile = blockIdx.x; tile < NTILES; tile += gridDim.x) {
        const int row0 = tile * 64;
        __syncthreads();
        for (int l = t; l < 64 * 16; l += 256) {
            int r = l >> 4, ch = l & 15;
            *(uint4*)&hb[PEH_OFF + r * P_STR + ch * 8] =
                *(const uint4*)(g_embh + (size_t)(row0 + r) * DD + ch * 8);
        }
        if (t < 64) e2_s[t] = g_e2[row0 + t];
        __syncthreads();

        // ---- GEMM1 (hi x hi): S = emb @ proto^T ----
        float sacc[4][4];
#pragma unroll
        for (int i = 0; i < 4; i++)
#pragma unroll
            for (int j = 0; j < 4; j++) sacc[i][j] = 0.f;
#pragma unroll
        for (int ks = 0; ks < 8; ks++) {
            const int kk = ks * 16;
            uint32_t ah4[4];
            ldm_x4(ah4, hbase + 2 * (PEH_OFF + (warp_m * 16 + lr) * P_STR + kk + lc * 8));
            uint32_t bh[4][2];
#pragma unroll
            for (int nb = 0; nb < 2; nb++) {
                uint32_t r4[4];
                ldm_x4(r4, hbase + 2 * (PPH_OFF + (warp_n * 32 + nb * 16 + lr) * P_STR + kk + lc * 8));
                bh[nb * 2][0] = r4[0]; bh[nb * 2][1] = r4[2];
                bh[nb * 2 + 1][0] = r4[1]; bh[nb * 2 + 1][1] = r4[3];
            }
#pragma unroll
            for (int fn = 0; fn < 4; fn++)
                mma16816(sacc[fn], ah4, bh[fn]);
        }
        {
            const int rr = warp_m * 16 + (lane >> 2);
#pragma unroll
            for (int fn = 0; fn < 4; fn++) {
                const int cc = warp_n * 32 + fn * 8 + (lane & 3) * 2;
                S_sh[rr * 65 + cc] =
                    sqrtf(fmaxf(e2_s[rr] + p2_s[cc] - 2.f * sacc[fn][0], 0.f));
                S_sh[rr * 65 + cc + 1] =
                    sqrtf(fmaxf(e2_s[rr] + p2_s[cc + 1] - 2.f * sacc[fn][1], 0.f));
                S_sh[(rr + 8) * 65 + cc] =
                    sqrtf(fmaxf(e2_s[rr + 8] + p2_s[cc] - 2.f * sacc[fn][2], 0.f));
                S_sh[(rr + 8) * 65 + cc + 1] =
                    sqrtf(fmaxf(e2_s[rr + 8] + p2_s[cc + 1] - 2.f * sacc[fn][3], 0.f));
            }
        }
        __syncthreads();

        // ---- softmax; attn stored as plain bf16 ----
        {
            const int r = t >> 2, sg = t & 3;
            const int cbase = sg * 16;
            float mn = 1e30f;
#pragma unroll
            for (int i = 0; i < 16; i++) mn = fminf(mn, S_sh[r * 65 + cbase + i]);
            mn = fminf(mn, __shfl_xor_sync(0xffffffffu, mn, 1));
            mn = fminf(mn, __shfl_xor_sync(0xffffffffu, mn, 2));
            float w[16];
            float s = 0.f;
#pragma unroll
            for (int i = 0; i < 16; i++) {
                w[i] = __expf(mn - S_sh[r * 65 + cbase + i]);
                s += w[i];
            }
            s += __shfl_xor_sync(0xffffffffu, s, 1);
            s += __shfl_xor_sync(0xffffffffu, s, 2);
            const float inv = 1.0f / s;
#pragma unroll
            for (int i = 0; i < 16; i += 2)
                *(uint32_t*)&hb[PAH_OFF + r * AT_STR + cbase + i] =
                    pack2(__float2bfloat16_rn(w[i] * inv),
                          __float2bfloat16_rn(w[i + 1] * inv));
        }
        __syncthreads();

        // ---- GEMM2 (hi x hi): acc += attn^T @ emb ----
#pragma unroll
        for (int ks = 0; ks < 4; ks++) {
            const int kk = ks * 16;
            uint32_t r4[4];
            uint32_t aa_h[4];
            ldm_x4_t(r4, hbase + 2 * (PAH_OFF + (kk + lr) * AT_STR + warp_m * 16 + lc * 8));
            aa_h[0] = r4[0]; aa_h[1] = r4[2]; aa_h[2] = r4[1]; aa_h[3] = r4[3];
#pragma unroll
            for (int nb = 0; nb < 4; nb++) {
                uint32_t e4[4];
                uint32_t beh0[2], beh1[2];
                ldm_x4_t(e4, hbase + 2 * (PEH_OFF + (kk + lr) * P_STR + warp_n * 64 + nb * 16 + lc * 8));
                beh0[0] = e4[0]; beh0[1] = e4[1];
                beh1[0] = e4[2]; beh1[1] = e4[3];
                mma16816(acc[nb * 2],     aa_h, beh0);
                mma16816(acc[nb * 2 + 1], aa_h, beh1);
            }
        }
    }
    {
        const int cr = warp_m * 16 + (lane >> 2);
#pragma unroll
        for (int fn = 0; fn < 8; fn++) {
            const int dc = warp_n * 64 + fn * 8 + (lane & 3) * 2;
            atomicAdd(&g_sums[cr * DD + dc],           acc[fn][0]);
            atomicAdd(&g_sums[cr * DD + dc + 1],       acc[fn][1]);
            atomicAdd(&g_sums[(cr + 8) * DD + dc],     acc[fn][2]);
            atomicAdd(&g_sums[(cr + 8) * DD + dc + 1], acc[fn][3]);
        }
    }
}

// ---------------- 3c. finalize prototypes (+ re-zero g_sums) ----------------
__global__ __launch_bounds__(128) void k_final() {
    __shared__ float red[128];
    const int c = blockIdx.x, d = threadIdx.x;
    float p = g_sums[c * DD + d] * (1.0f / (float)NTOT);
    g_sums[c * DD + d] = 0.f;
    g_proto[c * DD + d] = p;
    __nv_bfloat16 h, l;
    split1(p, h, l);
    g_ph[c * DD + d] = h;
    g_pl[c * DD + d] = l;
    red[d] = p * p;
    __syncthreads();
    for (int o = 64; o > 0; o >>= 1) {
        if (d < o) red[d] += red[d + o];
        __syncthreads();
    }
    if (d == 0) g_p2[c] = red[0];
}

// ---------------- 4. query logits via mma (full 3-product split) ------------
__global__ __launch_bounds__(256) void k_logits(float* __restrict__ out) {
    extern __shared__ char sm[];
    float* S_sh = (float*)sm;                // [64][65]
    float* e2_s = S_sh + 64 * 65;
    float* p2_s = e2_s + 64;
    __nv_bfloat16* hb = (__nv_bfloat16*)(sm + FP32_BYTES);
    const uint32_t hbase = smem_u32(sm) + FP32_BYTES;

    const int t = threadIdx.x, wid = t >> 5, lane = t & 31;
    const int lr = lane & 15, lc = lane >> 4;
    const int warp_m = wid & 3, warp_n = wid >> 2;

    for (int l = t; l < 64 * 16; l += 256) {
        int r = l >> 4, ch = l & 15;
        *(uint4*)&hb[PH_OFF + r * P_STR + ch * 8] = *(const uint4*)(g_ph + r * DD + ch * 8);
        *(uint4*)&hb[PL_OFF + r * P_STR + ch * 8] = *(const uint4*)(g_pl + r * DD + ch * 8);
    }
    if (t < 64) p2_s[t] = g_p2[t];

    const int q0 = blockIdx.x * 64;
    const int row0 = NS + q0;
    for (int l = t; l < 64 * 16; l += 256) {
        int r = l >> 4, ch = l & 15;
        *(uint4*)&hb[EH_OFF + r * P_STR + ch * 8] =
            *(const uint4*)(g_embh + (size_t)(row0 + r) * DD + ch * 8);
        *(uint4*)&hb[EL_OFF + r * P_STR + ch * 8] =
            *(const uint4*)(g_embl + (size_t)(row0 + r) * DD + ch * 8);
    }
    if (t < 64) e2_s[t] = g_e2[row0 + t];
    __syncthreads();

    float sacc[4][4];
#pragma unroll
    for (int i = 0; i < 4; i++)
#pragma unroll
        for (int j = 0; j < 4; j++) sacc[i][j] = 0.f;
#pragma unroll
    for (int ks = 0; ks < 8; ks++) {
        const int kk = ks * 16;
        uint32_t ah4[4], al4[4];
        ldm_x4(ah4, hbase + 2 * (EH_OFF + (warp_m * 16 + lr) * P_STR + kk + lc * 8));
        ldm_x4(al4, hbase + 2 * (EL_OFF + (warp_m * 16 + lr) * P_STR + kk + lc * 8));
        uint32_t bh[4][2], bl[4][2];
#pragma unroll
        for (int nb = 0; nb < 2; nb++) {
            uint32_t r4[4];
            ldm_x4(r4, hbase + 2 * (PH_OFF + (warp_n * 32 + nb * 16 + lr) * P_STR + kk + lc * 8));
            bh[nb * 2][0] = r4[0]; bh[nb * 2][1] = r4[2];
            bh[nb * 2 + 1][0] = r4[1]; bh[nb * 2 + 1][1] = r4[3];
            ldm_x4(r4, hbase + 2 * (PL_OFF + (warp_n * 32 + nb * 16 + lr) * P_STR + kk + lc * 8));
            bl[nb * 2][0] = r4[0]; bl[nb * 2][1] = r4[2];
            bl[nb * 2 + 1][0] = r4[1]; bl[nb * 2 + 1][1] = r4[3];
        }
#pragma unroll
        for (int fn = 0; fn < 4; fn++) {
            mma16816(sacc[fn], ah4, bh[fn]);
            mma16816(sacc[fn], ah4, bl[fn]);
            mma16816(sacc[fn], al4, bh[fn]);
        }
    }
    {
        const int rr = warp_m * 16 + (lane >> 2);
#pragma unroll
        for (int fn = 0; fn < 4; fn++) {
            const int cc = warp_n * 32 + fn * 8 + (lane & 3) * 2;
            S_sh[rr * 65 + cc] =
                -sqrtf(fmaxf(e2_s[rr] + p2_s[cc] - 2.f * sacc[fn][0], 0.f));
            S_sh[rr * 65 + cc + 1] =
                -sqrtf(fmaxf(e2_s[rr] + p2_s[cc + 1] - 2.f * sacc[fn][1], 0.f));
            S_sh[(rr + 8) * 65 + cc] =
                -sqrtf(fmaxf(e2_s[rr + 8] + p2_s[cc] - 2.f * sacc[fn][2], 0.f));
            S_sh[(rr + 8) * 65 + cc + 1] =
                -sqrtf(fmaxf(e2_s[rr + 8] + p2_s[cc + 1] - 2.f * sacc[fn][3], 0.f));
        }
    }
    __syncthreads();
    for (int l = t; l < 64 * CC; l += 256) {
        int r = l >> 6, c = l & 63;
        out[(size_t)(q0 + r) * CC + c] = S_sh[r * 65 + c];
    }
}

// ---------------- launch ----------------------------------------------------
extern "C" void kernel_launch(void* const* d_in, const int* in_sizes, int n_in,
                              void* d_out, int out_size) {
    const float* sup = (const float*)d_in[0];
    const float* qry = (const float*)d_in[1];
    const int*   lab = (const int*)d_in[2];
    const float* W   = (const float*)d_in[3];
    const float* b   = (const float*)d_in[4];
    float* out = (float*)d_out;

    cudaFuncSetAttribute(k_prop,   cudaFuncAttributeMaxDynamicSharedMemorySize, PROP_SMEM);
    cudaFuncSetAttribute(k_logits, cudaFuncAttributeMaxDynamicSharedMemorySize, LOG_SMEM);
    cudaFuncSetAttribute(k_embed_mma, cudaFuncAttributeMaxDynamicSharedMemorySize, EMB_SMEM_BYTES);
    cudaFuncSetAttribute(k_prop,   cudaFuncAttributePreferredSharedMemoryCarveout, 100);
    cudaFuncSetAttribute(k_logits, cudaFuncAttributePreferredSharedMemoryCarveout, 100);
    cudaFuncSetAttribute(k_embed_mma, cudaFuncAttributePreferredSharedMemoryCarveout, 100);

    k_wconv<<<64, 1024>>>(W);
    k_embed_mma<<<MTILES, 256, EMB_SMEM_BYTES>>>(sup, qry, b);
    k_init<<<CC, 128>>>(lab);
    for (int it = 0; it < 3; it++) {
        k_prop<<<PROP_GRID, 256, PROP_SMEM>>>();
        k_final<<<CC, 128>>>();
    }
    k_logits<<<QTILES, 256, LOG_SMEM>>>(out);
}

// round 16
// speedup vs baseline: 1.2508x; 1.1213x over previous
#include <cuda_runtime.h>
#include <cuda_bf16.h>
#include <cuda_fp16.h>
#include <math.h>
#include <stdint.h>

#define NS    3200
#define NQ    200000
#define NTOT  203200        // NS + NQ
#define INF_  512
#define DD    128
#define CC    64
#define NTILES   (NTOT/64)  // 3175
#define QTILES   (NQ/64)    // 3125
#define MTILES   ((NTOT + 127) / 128)   // 1588

// ---------------- scratch (device globals; no allocation allowed) ----------
__device__ float g_embS[(size_t)NS * DD];        // fp32 support embeddings
__device__ __nv_bfloat16 g_embh[(size_t)NTOT * DD];  // emb hi
__device__ __nv_bfloat16 g_embl[(size_t)NTOT * DD];  // emb lo
__device__ float g_e2[NTOT];                 // per-row squared norms
__device__ float g_proto[CC * DD];           // prototypes fp32 [64][128]
__device__ __nv_bfloat16 g_ph[CC * DD];      // proto hi
__device__ __nv_bfloat16 g_pl[CC * DD];      // proto lo
__device__ float g_p2[CC];                   // proto squared norms
__device__ float g_sums[CC * DD];            // accumulation buffer
__device__ __half g_wh16[INF_ * DD];         // W fp16 [512][128]

// ================= helpers ==================================================
__device__ __forceinline__ uint32_t smem_u32(const void* p) {
    uint32_t a;
    asm("{ .reg .u64 t; cvta.to.shared.u64 t, %1; cvt.u32.u64 %0, t; }"
        : "=r"(a) : "l"(p));
    return a;
}
__device__ __forceinline__ void mma16816(float* d, const uint32_t* a, const uint32_t* b) {
    asm volatile(
        "mma.sync.aligned.m16n8k16.row.col.f32.bf16.bf16.f32 "
        "{%0,%1,%2,%3}, {%4,%5,%6,%7}, {%8,%9}, {%0,%1,%2,%3};\n"
        : "+f"(d[0]), "+f"(d[1]), "+f"(d[2]), "+f"(d[3])
        : "r"(a[0]), "r"(a[1]), "r"(a[2]), "r"(a[3]), "r"(b[0]), "r"(b[1]));
}
__device__ __forceinline__ void mma16816h(float* d, const uint32_t* a, const uint32_t* b) {
    asm volatile(
        "mma.sync.aligned.m16n8k16.row.col.f32.f16.f16.f32 "
        "{%0,%1,%2,%3}, {%4,%5,%6,%7}, {%8,%9}, {%0,%1,%2,%3};\n"
        : "+f"(d[0]), "+f"(d[1]), "+f"(d[2]), "+f"(d[3])
        : "r"(a[0]), "r"(a[1]), "r"(a[2]), "r"(a[3]), "r"(b[0]), "r"(b[1]));
}
__device__ __forceinline__ void ldm_x4(uint32_t* r, uint32_t addr) {
    asm volatile("ldmatrix.sync.aligned.m8n8.x4.shared.b16 {%0,%1,%2,%3}, [%4];\n"
                 : "=r"(r[0]), "=r"(r[1]), "=r"(r[2]), "=r"(r[3]) : "r"(addr));
}
__device__ __forceinline__ void ldm_x4_t(uint32_t* r, uint32_t addr) {
    asm volatile("ldmatrix.sync.aligned.m8n8.x4.trans.shared.b16 {%0,%1,%2,%3}, [%4];\n"
                 : "=r"(r[0]), "=r"(r[1]), "=r"(r[2]), "=r"(r[3]) : "r"(addr));
}
__device__ __forceinline__ uint32_t pack2(__nv_bfloat16 a, __nv_bfloat16 b) {
    return ((uint32_t)__bfloat16_as_ushort(b) << 16) | (uint32_t)__bfloat16_as_ushort(a);
}
__device__ __forceinline__ uint32_t pack2h(__half a, __half b) {
    return ((uint32_t)__half_as_ushort(b) << 16) | (uint32_t)__half_as_ushort(a);
}
__device__ __forceinline__ void split1(float x, __nv_bfloat16& h, __nv_bfloat16& l) {
    h = __float2bfloat16_rn(x);
    l = __float2bfloat16_rn(x - __bfloat162float(h));
}

// ---------------- 0. W convert to fp16 (natural [K][N] layout) --------------
__global__ void k_wconv(const float* __restrict__ W) {
    int i = blockIdx.x * blockDim.x + threadIdx.x;
    if (i < INF_ * DD)
        g_wh16[i] = __float2half_rn(W[i]);
}

// ---------------- 1. embedding GEMM via mma.sync fp16 single-pass -----------
// R6-proven dataflow (LDG->cvt->STS, single buffer, 256 threads), fp16 hi-only.
// smem tiles (halves): AH [128][72] @0, BH [64][136] @9216; epilogue staging
// [128][132] f32 sets the footprint.
#define A_STR 72
#define B_STR 136
#define AH16_OFF 0
#define BH16_OFF (128 * A_STR)                  // 9216
#define EMB_SMEM_BYTES (128 * 132 * 4)          // 67584 (epilogue dominates)
#define C_STR 132

__global__ __launch_bounds__(256)
void k_embed_mma(const float* __restrict__ sup, const float* __restrict__ qry,
                 const float* __restrict__ bias) {
    extern __shared__ char smraw[];
    __half* sh = (__half*)smraw;
    float* shf = (float*)smraw;
    const uint32_t sbase = smem_u32(smraw);

    const int t = threadIdx.x;
    const int wid = t >> 5, lane = t & 31;
    const int warp_m = wid & 3;
    const int warp_n = wid >> 2;
    const int m0 = blockIdx.x * 128;
    const int lr = lane & 15;
    const int lc = lane >> 4;

    float acc[2][8][4];
#pragma unroll
    for (int i = 0; i < 2; i++)
#pragma unroll
        for (int j = 0; j < 8; j++)
#pragma unroll
            for (int q = 0; q < 4; q++) acc[i][j][q] = 0.f;

    for (int kb = 0; kb < 8; kb++) {
        const int k0 = kb * 64;
        __syncthreads();
        // ---- A: 128 rows x 64 k fp32 -> fp16 -> STS (2048 float4) ----
#pragma unroll
        for (int p = 0; p < 8; p++) {
            int l = t + 256 * p;
            int r = l >> 4, q = l & 15;
            int row = m0 + r;
            if (row >= NTOT) row = NTOT - 1;
            const float* src = (row < NS) ? (sup + (size_t)row * INF_)
                                          : (qry + (size_t)(row - NS) * INF_);
            float4 v = *(const float4*)(src + k0 + q * 4);
            *(uint2*)&sh[AH16_OFF + r * A_STR + q * 4] =
                make_uint2(pack2h(__float2half_rn(v.x), __float2half_rn(v.y)),
                           pack2h(__float2half_rn(v.z), __float2half_rn(v.w)));
        }
        // ---- B: 64 k-rows x 128 n fp16 (1024 uint4, 4/thread) ----
#pragma unroll
        for (int p = 0; p < 4; p++) {
            int l = t + 256 * p;
            int kr = l >> 4, ch = l & 15;
            *(uint4*)&sh[BH16_OFF + kr * B_STR + ch * 8] =
                *(const uint4*)(g_wh16 + (size_t)(k0 + kr) * DD + ch * 8);
        }
        __syncthreads();

        // ---- compute 4 k16 steps (single fp16 product) ----
#pragma unroll
        for (int ks = 0; ks < 4; ks++) {
            const int kk = ks * 16;
            uint32_t bh[8][2];
#pragma unroll
            for (int nb = 0; nb < 4; nb++) {
                uint32_t r4[4];
                uint32_t addr = sbase + 2 * (BH16_OFF + (kk + lr) * B_STR
                                 + warp_n * 64 + nb * 16 + lc * 8);
                ldm_x4_t(r4, addr);
                bh[nb * 2][0] = r4[0]; bh[nb * 2][1] = r4[1];
                bh[nb * 2 + 1][0] = r4[2]; bh[nb * 2 + 1][1] = r4[3];
            }
#pragma unroll
            for (int fm = 0; fm < 2; fm++) {
                uint32_t ah[4];
                int arow = warp_m * 32 + fm * 16 + lr;
                ldm_x4(ah, sbase + 2 * (AH16_OFF + arow * A_STR + kk + lc * 8));
#pragma unroll
                for (int fn = 0; fn < 8; fn++)
                    mma16816h(acc[fm][fn], ah, bh[fn]);
            }
        }
    }

    // ---- epilogue: stage C via smem; bias; fp32 (support) + bf16 hi/lo + e2 ----
    __syncthreads();
#pragma unroll
    for (int fm = 0; fm < 2; fm++)
#pragma unroll
        for (int fn = 0; fn < 8; fn++) {
            int r0 = warp_m * 32 + fm * 16 + (lane >> 2);
            int c0 = warp_n * 64 + fn * 8 + (lane & 3) * 2;
            shf[r0 * C_STR + c0]           = acc[fm][fn][0];
            shf[r0 * C_STR + c0 + 1]       = acc[fm][fn][1];
            shf[(r0 + 8) * C_STR + c0]     = acc[fm][fn][2];
            shf[(r0 + 8) * C_STR + c0 + 1] = acc[fm][fn][3];
        }
    __syncthreads();
    {
        const int r = t >> 1, half = t & 1;
        const int row = m0 + r;
        float e2 = 0.f;
        if (row < NTOT) {
            const float* srow = &shf[r * C_STR + half * 64];
            __nv_bfloat16* dh = g_embh + (size_t)row * DD + half * 64;
            __nv_bfloat16* dl = g_embl + (size_t)row * DD + half * 64;
#pragma unroll
            for (int j = 0; j < 64; j += 4) {
                float4 o;
                o.x = srow[j + 0] + __ldg(bias + half * 64 + j + 0);
                o.y = srow[j + 1] + __ldg(bias + half * 64 + j + 1);
                o.z = srow[j + 2] + __ldg(bias + half * 64 + j + 2);
                o.w = srow[j + 3] + __ldg(bias + half * 64 + j + 3);
                if (row < NS)
                    *(float4*)(g_embS + (size_t)row * DD + half * 64 + j) = o;
                __nv_bfloat16 h0, l0, h1, l1, h2, l2, h3, l3;
                split1(o.x, h0, l0); split1(o.y, h1, l1);
                split1(o.z, h2, l2); split1(o.w, h3, l3);
                *(uint2*)(dh + j) = make_uint2(pack2(h0, h1), pack2(h2, h3));
                *(uint2*)(dl + j) = make_uint2(pack2(l0, l1), pack2(l2, l3));
                e2 += o.x * o.x + o.y * o.y + o.z * o.z + o.w * o.w;
            }
        }
        float e2o = __shfl_xor_sync(0xffffffffu, e2, 1);
        if (half == 0 && row < NTOT) g_e2[row] = e2 + e2o;
    }
}

// ---------------- 2. initial prototypes: segment mean (+ zero g_sums) ------
__global__ __launch_bounds__(128) void k_init(const int* __restrict__ lab) {
    __shared__ float red[128];
    const int c = blockIdx.x, d = threadIdx.x;
    g_sums[c * DD + d] = 0.f;
    float sum = 0.f; int cnt = 0;
    for (int n = 0; n < NS; n++) {
        if (__ldg(&lab[n]) == c) { sum += g_embS[(size_t)n * DD + d]; cnt++; }
    }
    float p = sum / fmaxf((float)cnt, 1.0f);
    g_proto[c * DD + d] = p;
    __nv_bfloat16 h, l;
    split1(p, h, l);
    g_ph[c * DD + d] = h;
    g_pl[c * DD + d] = l;
    red[d] = p * p;
    __syncthreads();
    for (int o = 64; o > 0; o >>= 1) {
        if (d < o) red[d] += red[d + o];
        __syncthreads();
    }
    if (d == 0) g_p2[c] = red[0];
}

// ---------------- 3b. fused attention + prototype accumulation (mma) -------
// R10/R14-proven config: HI-ONLY, separate AH buffer, 61184 B smem, grid 444.
#define FP32_BYTES 17152
#define PPH_OFF 0
#define PEH_OFF 8704
#define PAH_OFF 17408
#define PROP_SMEM (FP32_BYTES + (17408 + 64 * 72) * 2)   // 61184
#define P_STR 136
#define AT_STR 72
#define PH_OFF 0
#define PL_OFF 8704
#define EH_OFF 17408
#define EL_OFF 26112
#define LOG_SMEM (FP32_BYTES + 34816 * 2)                // 86784
#define PROP_GRID 444

__global__ __launch_bounds__(256) void k_prop() {
    extern __shared__ char sm[];
    float* S_sh = (float*)sm;                // [64][65]
    float* e2_s = S_sh + 64 * 65;
    float* p2_s = e2_s + 64;
    __nv_bfloat16* hb = (__nv_bfloat16*)(sm + FP32_BYTES);
    const uint32_t hbase = smem_u32(sm) + FP32_BYTES;

    const int t = threadIdx.x, wid = t >> 5, lane = t & 31;
    const int lr = lane & 15, lc = lane >> 4;
    const int warp_m = wid & 3, warp_n = wid >> 2;

    for (int l = t; l < 64 * 16; l += 256) {
        int r = l >> 4, ch = l & 15;
        *(uint4*)&hb[PPH_OFF + r * P_STR + ch * 8] = *(const uint4*)(g_ph + r * DD + ch * 8);
    }
    if (t < 64) p2_s[t] = g_p2[t];

    float acc[8][4];
#pragma unroll
    for (int j = 0; j < 8; j++)
#pragma unroll
        for (int q = 0; q < 4; q++) acc[j][q] = 0.f;

    for (int tile = blockIdx.x; tile < NTILES; tile += gridDim.x) {
        const int row0 = tile * 64;
        __syncthreads();
        for (int l = t; l < 64 * 16; l += 256) {
            int r = l >> 4, ch = l & 15;
            *(uint4*)&hb[PEH_OFF + r * P_STR + ch * 8] =
                *(const uint4*)(g_embh + (size_t)(row0 + r) * DD + ch * 8);
        }
        if (t < 64) e2_s[t] = g_e2[row0 + t];
        __syncthreads();

        // ---- GEMM1 (hi x hi): S = emb @ proto^T ----
        float sacc[4][4];
#pragma unroll
        for (int i = 0; i < 4; i++)
#pragma unroll
            for (int j = 0; j < 4; j++) sacc[i][j] = 0.f;
#pragma unroll
        for (int ks = 0; ks < 8; ks++) {
            const int kk = ks * 16;
            uint32_t ah4[4];
            ldm_x4(ah4, hbase + 2 * (PEH_OFF + (warp_m * 16 + lr) * P_STR + kk + lc * 8));
            uint32_t bh[4][2];
#pragma unroll
            for (int nb = 0; nb < 2; nb++) {
                uint32_t r4[4];
                ldm_x4(r4, hbase + 2 * (PPH_OFF + (warp_n * 32 + nb * 16 + lr) * P_STR + kk + lc * 8));
                bh[nb * 2][0] = r4[0]; bh[nb * 2][1] = r4[2];
                bh[nb * 2 + 1][0] = r4[1]; bh[nb * 2 + 1][1] = r4[3];
            }
#pragma unroll
            for (int fn = 0; fn < 4; fn++)
                mma16816(sacc[fn], ah4, bh[fn]);
        }
        {
            const int rr = warp_m * 16 + (lane >> 2);
#pragma unroll
            for (int fn = 0; fn < 4; fn++) {
                const int cc = warp_n * 32 + fn * 8 + (lane & 3) * 2;
                S_sh[rr * 65 + cc] =
                    sqrtf(fmaxf(e2_s[rr] + p2_s[cc] - 2.f * sacc[fn][0], 0.f));
                S_sh[rr * 65 + cc + 1] =
                    sqrtf(fmaxf(e2_s[rr] + p2_s[cc + 1] - 2.f * sacc[fn][1], 0.f));
                S_sh[(rr + 8) * 65 + cc] =
                    sqrtf(fmaxf(e2_s[rr + 8] + p2_s[cc] - 2.f * sacc[fn][2], 0.f));
                S_sh[(rr + 8) * 65 + cc + 1] =
                    sqrtf(fmaxf(e2_s[rr + 8] + p2_s[cc + 1] - 2.f * sacc[fn][3], 0.f));
            }
        }
        __syncthreads();

        // ---- softmax; attn stored as plain bf16 ----
        {
            const int r = t >> 2, sg = t & 3;
            const int cbase = sg * 16;
            float mn = 1e30f;
#pragma unroll
            for (int i = 0; i < 16; i++) mn = fminf(mn, S_sh[r * 65 + cbase + i]);
            mn = fminf(mn, __shfl_xor_sync(0xffffffffu, mn, 1));
            mn = fminf(mn, __shfl_xor_sync(0xffffffffu, mn, 2));
            float w[16];
            float s = 0.f;
#pragma unroll
            for (int i = 0; i < 16; i++) {
                w[i] = __expf(mn - S_sh[r * 65 + cbase + i]);
                s += w[i];
            }
            s += __shfl_xor_sync(0xffffffffu, s, 1);
            s += __shfl_xor_sync(0xffffffffu, s, 2);
            const float inv = 1.0f / s;
#pragma unroll
            for (int i = 0; i < 16; i += 2)
                *(uint32_t*)&hb[PAH_OFF + r * AT_STR + cbase + i] =
                    pack2(__float2bfloat16_rn(w[i] * inv),
                          __float2bfloat16_rn(w[i + 1] * inv));
        }
        __syncthreads();

        // ---- GEMM2 (hi x hi): acc += attn^T @ emb ----
#pragma unroll
        for (int ks = 0; ks < 4; ks++) {
            const int kk = ks * 16;
            uint32_t r4[4];
            uint32_t aa_h[4];
            ldm_x4_t(r4, hbase + 2 * (PAH_OFF + (kk + lr) * AT_STR + warp_m * 16 + lc * 8));
            aa_h[0] = r4[0]; aa_h[1] = r4[2]; aa_h[2] = r4[1]; aa_h[3] = r4[3];
#pragma unroll
            for (int nb = 0; nb < 4; nb++) {
                uint32_t e4[4];
                uint32_t beh0[2], beh1[2];
                ldm_x4_t(e4, hbase + 2 * (PEH_OFF + (kk + lr) * P_STR + warp_n * 64 + nb * 16 + lc * 8));
                beh0[0] = e4[0]; beh0[1] = e4[1];
                beh1[0] = e4[2]; beh1[1] = e4[3];
                mma16816(acc[nb * 2],     aa_h, beh0);
                mma16816(acc[nb * 2 + 1], aa_h, beh1);
            }
        }
    }
    {
        const int cr = warp_m * 16 + (lane >> 2);
#pragma unroll
        for (int fn = 0; fn < 8; fn++) {
            const int dc = warp_n * 64 + fn * 8 + (lane & 3) * 2;
            atomicAdd(&g_sums[cr * DD + dc],           acc[fn][0]);
            atomicAdd(&g_sums[cr * DD + dc + 1],       acc[fn][1]);
            atomicAdd(&g_sums[(cr + 8) * DD + dc],     acc[fn][2]);
            atomicAdd(&g_sums[(cr + 8) * DD + dc + 1], acc[fn][3]);
        }
    }
}

// ---------------- 3c. finalize prototypes (+ re-zero g_sums) ----------------
__global__ __launch_bounds__(128) void k_final() {
    __shared__ float red[128];
    const int c = blockIdx.x, d = threadIdx.x;
    float p = g_sums[c * DD + d] * (1.0f / (float)NTOT);
    g_sums[c * DD + d] = 0.f;
    g_proto[c * DD + d] = p;
    __nv_bfloat16 h, l;
    split1(p, h, l);
    g_ph[c * DD + d] = h;
    g_pl[c * DD + d] = l;
    red[d] = p * p;
    __syncthreads();
    for (int o = 64; o > 0; o >>= 1) {
        if (d < o) red[d] += red[d + o];
        __syncthreads();
    }
    if (d == 0) g_p2[c] = red[0];
}

// ---------------- 4. query logits via mma (full 3-product split) ------------
__global__ __launch_bounds__(256) void k_logits(float* __restrict__ out) {
    extern __shared__ char sm[];
    float* S_sh = (float*)sm;                // [64][65]
    float* e2_s = S_sh + 64 * 65;
    float* p2_s = e2_s + 64;
    __nv_bfloat16* hb = (__nv_bfloat16*)(sm + FP32_BYTES);
    const uint32_t hbase = smem_u32(sm) + FP32_BYTES;

    const int t = threadIdx.x, wid = t >> 5, lane = t & 31;
    const int lr = lane & 15, lc = lane >> 4;
    const int warp_m = wid & 3, warp_n = wid >> 2;

    for (int l = t; l < 64 * 16; l += 256) {
        int r = l >> 4, ch = l & 15;
        *(uint4*)&hb[PH_OFF + r * P_STR + ch * 8] = *(const uint4*)(g_ph + r * DD + ch * 8);
        *(uint4*)&hb[PL_OFF + r * P_STR + ch * 8] = *(const uint4*)(g_pl + r * DD + ch * 8);
    }
    if (t < 64) p2_s[t] = g_p2[t];

    const int q0 = blockIdx.x * 64;
    const int row0 = NS + q0;
    for (int l = t; l < 64 * 16; l += 256) {
        int r = l >> 4, ch = l & 15;
        *(uint4*)&hb[EH_OFF + r * P_STR + ch * 8] =
            *(const uint4*)(g_embh + (size_t)(row0 + r) * DD + ch * 8);
        *(uint4*)&hb[EL_OFF + r * P_STR + ch * 8] =
            *(const uint4*)(g_embl + (size_t)(row0 + r) * DD + ch * 8);
    }
    if (t < 64) e2_s[t] = g_e2[row0 + t];
    __syncthreads();

    float sacc[4][4];
#pragma unroll
    for (int i = 0; i < 4; i++)
#pragma unroll
        for (int j = 0; j < 4; j++) sacc[i][j] = 0.f;
#pragma unroll
    for (int ks = 0; ks < 8; ks++) {
        const int kk = ks * 16;
        uint32_t ah4[4], al4[4];
        ldm_x4(ah4, hbase + 2 * (EH_OFF + (warp_m * 16 + lr) * P_STR + kk + lc * 8));
        ldm_x4(al4, hbase + 2 * (EL_OFF + (warp_m * 16 + lr) * P_STR + kk + lc * 8));
        uint32_t bh[4][2], bl[4][2];
#pragma unroll
        for (int nb = 0; nb < 2; nb++) {
            uint32_t r4[4];
            ldm_x4(r4, hbase + 2 * (PH_OFF + (warp_n * 32 + nb * 16 + lr) * P_STR + kk + lc * 8));
            bh[nb * 2][0] = r4[0]; bh[nb * 2][1] = r4[2];
            bh[nb * 2 + 1][0] = r4[1]; bh[nb * 2 + 1][1] = r4[3];
            ldm_x4(r4, hbase + 2 * (PL_OFF + (warp_n * 32 + nb * 16 + lr) * P_STR + kk + lc * 8));
            bl[nb * 2][0] = r4[0]; bl[nb * 2][1] = r4[2];
            bl[nb * 2 + 1][0] = r4[1]; bl[nb * 2 + 1][1] = r4[3];
        }
#pragma unroll
        for (int fn = 0; fn < 4; fn++) {
            mma16816(sacc[fn], ah4, bh[fn]);
            mma16816(sacc[fn], ah4, bl[fn]);
            mma16816(sacc[fn], al4, bh[fn]);
        }
    }
    {
        const int rr = warp_m * 16 + (lane >> 2);
#pragma unroll
        for (int fn = 0; fn < 4; fn++) {
            const int cc = warp_n * 32 + fn * 8 + (lane & 3) * 2;
            S_sh[rr * 65 + cc] =
                -sqrtf(fmaxf(e2_s[rr] + p2_s[cc] - 2.f * sacc[fn][0], 0.f));
            S_sh[rr * 65 + cc + 1] =
                -sqrtf(fmaxf(e2_s[rr] + p2_s[cc + 1] - 2.f * sacc[fn][1], 0.f));
            S_sh[(rr + 8) * 65 + cc] =
                -sqrtf(fmaxf(e2_s[rr + 8] + p2_s[cc] - 2.f * sacc[fn][2], 0.f));
            S_sh[(rr + 8) * 65 + cc + 1] =
                -sqrtf(fmaxf(e2_s[rr + 8] + p2_s[cc + 1] - 2.f * sacc[fn][3], 0.f));
        }
    }
    __syncthreads();
    for (int l = t; l < 64 * CC; l += 256) {
        int r = l >> 6, c = l & 63;
        out[(size_t)(q0 + r) * CC + c] = S_sh[r * 65 + c];
    }
}

// ---------------- launch ----------------------------------------------------
extern "C" void kernel_launch(void* const* d_in, const int* in_sizes, int n_in,
                              void* d_out, int out_size) {
    const float* sup = (const float*)d_in[0];
    const float* qry = (const float*)d_in[1];
    const int*   lab = (const int*)d_in[2];
    const float* W   = (const float*)d_in[3];
    const float* b   = (const float*)d_in[4];
    float* out = (float*)d_out;

    cudaFuncSetAttribute(k_prop,   cudaFuncAttributeMaxDynamicSharedMemorySize, PROP_SMEM);
    cudaFuncSetAttribute(k_logits, cudaFuncAttributeMaxDynamicSharedMemorySize, LOG_SMEM);
    cudaFuncSetAttribute(k_embed_mma, cudaFuncAttributeMaxDynamicSharedMemorySize, EMB_SMEM_BYTES);
    cudaFuncSetAttribute(k_prop,   cudaFuncAttributePreferredSharedMemoryCarveout, 100);
    cudaFuncSetAttribute(k_logits, cudaFuncAttributePreferredSharedMemoryCarveout, 100);
    cudaFuncSetAttribute(k_embed_mma, cudaFuncAttributePreferredSharedMemoryCarveout, 100);

    k_wconv<<<64, 1024>>>(W);
    k_embed_mma<<<MTILES, 256, EMB_SMEM_BYTES>>>(sup, qry, b);
    k_init<<<CC, 128>>>(lab);
    for (int it = 0; it < 3; it++) {
        k_prop<<<PROP_GRID, 256, PROP_SMEM>>>();
        k_final<<<CC, 128>>>();
    }
    k_logits<<<QTILES, 256, LOG_SMEM>>>(out);
}